// round 13
// baseline (speedup 1.0000x reference)
#include <cuda_runtime.h>
#include <cuda_bf16.h>
#include <cfloat>
#include <math.h>
#include <cstdint>

#define BSZ 8
#define P1  8192
#define P2  2048
#define KNB 32
#define NQ  16384
#define NTOT 524288ull

typedef unsigned long long ull;

__device__ int    g_nn[NQ*KNB];
__device__ float  g_bufA[NTOT*64];    // y1 [n][64]
__device__ float  g_bufB[NTOT*64];    // y2 [n][64]
__device__ float  g_mx[NQ*128];
__device__ float  g_mn[NQ*128];
__device__ double g_sum[128];
__device__ double g_sqsum[128];
__device__ float  g_scale[3][128];
__device__ float  g_shift[3][128];
__device__ int    g_cnt[3];

static __device__ __forceinline__ uint32_t smem_u32(const void* p) {
    uint32_t a; asm("{ .reg .u64 t; cvta.to.shared.u64 t, %1; cvt.u32.u64 %0, t; }" : "=r"(a) : "l"(p));
    return a;
}
static __device__ __forceinline__ void ldsm4(uint32_t* r, uint32_t a) {
    asm volatile("ldmatrix.sync.aligned.m8n8.x4.shared.b16 {%0,%1,%2,%3}, [%4];"
        : "=r"(r[0]), "=r"(r[1]), "=r"(r[2]), "=r"(r[3]) : "r"(a));
}
static __device__ __forceinline__ void ldsm2(uint32_t* r, uint32_t a) {
    asm volatile("ldmatrix.sync.aligned.m8n8.x2.shared.b16 {%0,%1}, [%2];"
        : "=r"(r[0]), "=r"(r[1]) : "r"(a));
}
static __device__ __forceinline__ void mma16816(float* d, const uint32_t* a, const uint32_t* b) {
    asm volatile("mma.sync.aligned.m16n8k16.row.col.f32.bf16.bf16.f32 "
        "{%0,%1,%2,%3},{%4,%5,%6,%7},{%8,%9},{%0,%1,%2,%3};"
        : "+f"(d[0]), "+f"(d[1]), "+f"(d[2]), "+f"(d[3])
        : "r"(a[0]), "r"(a[1]), "r"(a[2]), "r"(a[3]), "r"(b[0]), "r"(b[1]));
}
static __device__ __forceinline__ void split1(float v, __nv_bfloat16 &h, __nv_bfloat16 &l) {
    h = __float2bfloat16_rn(v);
    l = __float2bfloat16_rn(v - __bfloat162float(h));
}
static __device__ __forceinline__ void split4(float4 v, uint2 &H, uint2 &L) {
    __nv_bfloat16 hx, hy, hz, hw, lx, ly, lz, lw;
    split1(v.x, hx, lx); split1(v.y, hy, ly);
    split1(v.z, hz, lz); split1(v.w, hw, lw);
    H.x = (uint32_t)__bfloat16_as_ushort(hx) | ((uint32_t)__bfloat16_as_ushort(hy) << 16);
    H.y = (uint32_t)__bfloat16_as_ushort(hz) | ((uint32_t)__bfloat16_as_ushort(hw) << 16);
    L.x = (uint32_t)__bfloat16_as_ushort(lx) | ((uint32_t)__bfloat16_as_ushort(ly) << 16);
    L.y = (uint32_t)__bfloat16_as_ushort(lz) | ((uint32_t)__bfloat16_as_ushort(lw) << 16);
}

// -------- KNN: warp per query, lane-sorted distributed top-32; SoA cache (96KB, 2 CTA/SM) --------
__global__ __launch_bounds__(1024) void knn_kernel(const float* __restrict__ xyz,
                           const int*   __restrict__ sidx,
                           float*       __restrict__ out_xyz) {
    extern __shared__ float sm[];
    float* sx = sm;            // [8192]
    float* sy = sm + P1;
    float* sz = sm + 2*P1;
    const int tid  = threadIdx.x;
    const int warp = tid >> 5, lane = tid & 31;
    const int qbase = blockIdx.x * 32;
    const int b = qbase / P2;
    const float* bx = xyz + (size_t)b * P1 * 3;

    for (int j = tid; j < P1; j += 1024) {
        sx[j] = bx[3*j]; sy[j] = bx[3*j+1]; sz[j] = bx[3*j+2];
    }
    __syncthreads();

    const int q  = qbase + warp;
    const int si = sidx[q];
    const float qx = bx[3*si], qy = bx[3*si+1], qz = bx[3*si+2];
    const float rA = __fadd_rn(__fadd_rn(__fmul_rn(qx,qx), __fmul_rn(qy,qy)), __fmul_rn(qz,qz));
    if (lane < 3) out_xyz[(size_t)q*3 + lane] = (lane == 0) ? qx : (lane == 1 ? qy : qz);

    float best_d = FLT_MAX; int best_i = 0;   // ascending across lanes
    float thr = FLT_MAX;

    for (int j0 = 0; j0 < P1; j0 += 32) {
        float x = sx[j0 + lane], y = sy[j0 + lane], z = sz[j0 + lane];
        float r2  = __fadd_rn(__fadd_rn(__fmul_rn(x,x), __fmul_rn(y,y)), __fmul_rn(z,z));
        float dot = __fmaf_rn(qz, z, __fmaf_rn(qy, y, __fmul_rn(qx, x)));
        float d   = __fadd_rn(__fsub_rn(rA, __fmul_rn(2.f, dot)), r2);
        unsigned m = __ballot_sync(0xffffffffu, d < thr);
        while (m) {
            int src = __ffs(m) - 1; m &= m - 1;
            float dc = __shfl_sync(0xffffffffu, d, src);
            unsigned bal = __ballot_sync(0xffffffffu, dc < best_d);
            if (bal) {
                int pos  = __ffs(bal) - 1;
                float ud = __shfl_up_sync(0xffffffffu, best_d, 1);
                int   ui = __shfl_up_sync(0xffffffffu, best_i, 1);
                if (lane > pos)       { best_d = ud; best_i = ui; }
                else if (lane == pos) { best_d = dc; best_i = j0 + src; }
            }
        }
        thr = __shfl_sync(0xffffffffu, best_d, 31);
    }
    g_nn[(size_t)q*KNB + lane] = best_i;
}

// -------- GEMM layer via mma.sync bf16 (3-term split), M=128/CTA; last-CTA BN finalize --------
template<int KPAD, int CIN, int N, int MODE, int POOL, int LAYER>
__global__ __launch_bounds__(256) void gemm_kernel(
        const float* __restrict__ feat, const float* __restrict__ xyz,
        const float* __restrict__ qxyz, const float* __restrict__ y_in,
        const float* __restrict__ W,    float* __restrict__ y_out,
        const float* __restrict__ gamma, const float* __restrict__ beta)
{
    extern __shared__ char smem[];
    constexpr int ST = KPAD + 8;
    constexpr int OFF_AH = 0;
    constexpr int OFF_AL = 128*ST*2;
    constexpr int OFF_BH = 2*OFF_AL;
    constexpr int OFF_BL = OFF_BH + N*ST*2;
    constexpr int OFF_S  = OFF_BL + N*ST*2;
    float* ssum = (float*)(smem + OFF_S);
    float* ssq  = ssum + N;
    __shared__ int isLast;
    const uint32_t sb = smem_u32(smem);
    const int tid = threadIdx.x;
    const int n0  = blockIdx.x * 128;
    const int cq  = tid & 15, rs = tid >> 4;

    if (tid < N) { ssum[tid] = 0.f; ssq[tid] = 0.f; }

    if (MODE == 0) {
        uint4 z = make_uint4(0,0,0,0);
        if (tid < 128 + N) {
            int isA = tid < 128;
            int row = isA ? tid : tid - 128;
            char* base = smem + (isA ? OFF_AH : OFF_BH) + row*ST*2 + 128;
            char* basl = smem + (isA ? OFF_AL : OFF_BL) + row*ST*2 + 128;
            *(uint4*)(base) = z;      *(uint4*)(base + 16) = z;
            *(uint4*)(basl) = z;      *(uint4*)(basl + 16) = z;
        }
        #pragma unroll
        for (int it = 0; it < 8; it++) {
            int row = rs + 16*it;
            int n   = n0 + row;
            int b   = n >> 16;
            int nn  = g_nn[n];
            float4 f = *(const float4*)(feat + (size_t)(b*P1 + nn)*64 + 4*cq);
            uint2 H, L; split4(f, H, L);
            *(uint2*)(smem + OFF_AH + row*ST*2 + 8*cq) = H;
            *(uint2*)(smem + OFF_AL + row*ST*2 + 8*cq) = L;
            if (cq == 0) {
                int q = n >> 5;
                const float* nx = xyz  + (size_t)(b*P1 + nn)*3;
                const float* qp = qxyz + (size_t)q*3;
                #pragma unroll
                for (int j = 0; j < 3; j++) {
                    __nv_bfloat16 h, l; split1(__fsub_rn(nx[j], qp[j]), h, l);
                    *(__nv_bfloat16*)(smem + OFF_AH + row*ST*2 + 128 + 2*j) = h;
                    *(__nv_bfloat16*)(smem + OFF_AL + row*ST*2 + 128 + 2*j) = l;
                }
            }
        }
        #pragma unroll
        for (int it = 0; it < N/16; it++) {
            int o = rs + 16*it;
            const float* wr = W + (size_t)o*CIN;
            float4 w4 = make_float4(wr[4*cq], wr[4*cq+1], wr[4*cq+2], wr[4*cq+3]);
            uint2 H, L; split4(w4, H, L);
            *(uint2*)(smem + OFF_BH + o*ST*2 + 8*cq) = H;
            *(uint2*)(smem + OFF_BL + o*ST*2 + 8*cq) = L;
            if (cq == 0) {
                #pragma unroll
                for (int j = 0; j < 3; j++) {
                    __nv_bfloat16 h, l; split1(wr[64 + j], h, l);
                    *(__nv_bfloat16*)(smem + OFF_BH + o*ST*2 + 128 + 2*j) = h;
                    *(__nv_bfloat16*)(smem + OFF_BL + o*ST*2 + 128 + 2*j) = l;
                }
            }
        }
    } else {
        const float4 sc4 = *(const float4*)(g_scale[LAYER-1] + 4*cq);
        const float4 sh4 = *(const float4*)(g_shift[LAYER-1] + 4*cq);
        #pragma unroll
        for (int it = 0; it < 8; it++) {
            int row = rs + 16*it;
            float4 v = *(const float4*)(y_in + (size_t)(n0 + row)*64 + 4*cq);
            v.x = fmaxf(__fmaf_rn(sc4.x, v.x, sh4.x), 0.f);
            v.y = fmaxf(__fmaf_rn(sc4.y, v.y, sh4.y), 0.f);
            v.z = fmaxf(__fmaf_rn(sc4.z, v.z, sh4.z), 0.f);
            v.w = fmaxf(__fmaf_rn(sc4.w, v.w, sh4.w), 0.f);
            uint2 H, L; split4(v, H, L);
            *(uint2*)(smem + OFF_AH + row*ST*2 + 8*cq) = H;
            *(uint2*)(smem + OFF_AL + row*ST*2 + 8*cq) = L;
        }
        #pragma unroll
        for (int it = 0; it < N/16; it++) {
            int o = rs + 16*it;
            float4 w4 = *(const float4*)(W + (size_t)o*64 + 4*cq);
            uint2 H, L; split4(w4, H, L);
            *(uint2*)(smem + OFF_BH + o*ST*2 + 8*cq) = H;
            *(uint2*)(smem + OFF_BL + o*ST*2 + 8*cq) = L;
        }
    }
    __syncthreads();

    const int w = tid >> 5, lane = tid & 31;
    const int mw = w & 3, nw = w >> 2;
    constexpr int NB = N/16;

    float acc[2][NB][4];
    #pragma unroll
    for (int mh = 0; mh < 2; mh++)
        #pragma unroll
        for (int nb = 0; nb < NB; nb++)
            #pragma unroll
            for (int j = 0; j < 4; j++) acc[mh][nb][j] = 0.f;

    const uint32_t aoff = ((mw*32 + (lane & 15))*ST + (lane >> 4)*8) * 2;
    const uint32_t boff = ((nw*(N/2) + (lane & 7))*ST + ((lane >> 3) & 1)*8) * 2;

    #pragma unroll
    for (int kk = 0; kk < KPAD/16; kk++) {
        uint32_t ah[2][4], al[2][4];
        #pragma unroll
        for (int mh = 0; mh < 2; mh++) {
            ldsm4(ah[mh], sb + OFF_AH + aoff + (mh*16*ST + kk*16)*2);
            ldsm4(al[mh], sb + OFF_AL + aoff + (mh*16*ST + kk*16)*2);
        }
        #pragma unroll
        for (int nb = 0; nb < NB; nb++) {
            uint32_t bh[2], bl[2];
            ldsm2(bh, sb + OFF_BH + boff + (nb*8*ST + kk*16)*2);
            ldsm2(bl, sb + OFF_BL + boff + (nb*8*ST + kk*16)*2);
            #pragma unroll
            for (int mh = 0; mh < 2; mh++) {
                mma16816(acc[mh][nb], ah[mh], bh);
                mma16816(acc[mh][nb], ah[mh], bl);
                mma16816(acc[mh][nb], al[mh], bh);
            }
        }
    }

    const int g = lane >> 2, t = lane & 3;
    #pragma unroll
    for (int nb = 0; nb < NB; nb++) {
        float s0 = acc[0][nb][0] + acc[0][nb][2] + acc[1][nb][0] + acc[1][nb][2];
        float s1 = acc[0][nb][1] + acc[0][nb][3] + acc[1][nb][1] + acc[1][nb][3];
        float q0 = acc[0][nb][0]*acc[0][nb][0] + acc[0][nb][2]*acc[0][nb][2]
                 + acc[1][nb][0]*acc[1][nb][0] + acc[1][nb][2]*acc[1][nb][2];
        float q1 = acc[0][nb][1]*acc[0][nb][1] + acc[0][nb][3]*acc[0][nb][3]
                 + acc[1][nb][1]*acc[1][nb][1] + acc[1][nb][3]*acc[1][nb][3];
        float mx0, mn0, mx1, mn1;
        if (POOL) {
            mx0 = fmaxf(fmaxf(acc[0][nb][0], acc[0][nb][2]), fmaxf(acc[1][nb][0], acc[1][nb][2]));
            mn0 = fminf(fminf(acc[0][nb][0], acc[0][nb][2]), fminf(acc[1][nb][0], acc[1][nb][2]));
            mx1 = fmaxf(fmaxf(acc[0][nb][1], acc[0][nb][3]), fmaxf(acc[1][nb][1], acc[1][nb][3]));
            mn1 = fminf(fminf(acc[0][nb][1], acc[0][nb][3]), fminf(acc[1][nb][1], acc[1][nb][3]));
        }
        #pragma unroll
        for (int off = 4; off < 32; off <<= 1) {
            s0 += __shfl_xor_sync(0xffffffffu, s0, off);
            s1 += __shfl_xor_sync(0xffffffffu, s1, off);
            q0 += __shfl_xor_sync(0xffffffffu, q0, off);
            q1 += __shfl_xor_sync(0xffffffffu, q1, off);
            if (POOL) {
                mx0 = fmaxf(mx0, __shfl_xor_sync(0xffffffffu, mx0, off));
                mn0 = fminf(mn0, __shfl_xor_sync(0xffffffffu, mn0, off));
                mx1 = fmaxf(mx1, __shfl_xor_sync(0xffffffffu, mx1, off));
                mn1 = fminf(mn1, __shfl_xor_sync(0xffffffffu, mn1, off));
            }
        }
        if (g == 0) {
            int col = nw*(N/2) + nb*8 + 2*t;
            atomicAdd(&ssum[col],   s0); atomicAdd(&ssum[col+1], s1);
            atomicAdd(&ssq[col],    q0); atomicAdd(&ssq[col+1],  q1);
            if (POOL) {
                int q = blockIdx.x*4 + mw;
                g_mx[(size_t)q*128 + col]   = mx0;  g_mn[(size_t)q*128 + col]   = mn0;
                g_mx[(size_t)q*128 + col+1] = mx1;  g_mn[(size_t)q*128 + col+1] = mn1;
            }
        }
    }

    if (!POOL) {
        #pragma unroll
        for (int mh = 0; mh < 2; mh++) {
            #pragma unroll
            for (int nb = 0; nb < NB; nb++) {
                int row = n0 + mw*32 + mh*16 + g;
                int col = nw*(N/2) + nb*8 + 2*t;
                *(float2*)(y_out + (size_t)row*N + col)       = make_float2(acc[mh][nb][0], acc[mh][nb][1]);
                *(float2*)(y_out + (size_t)(row + 8)*N + col) = make_float2(acc[mh][nb][2], acc[mh][nb][3]);
            }
        }
    }

    __syncthreads();
    if (tid < N) {
        atomicAdd(&g_sum[tid],   (double)ssum[tid]);
        atomicAdd(&g_sqsum[tid], (double)ssq[tid]);
    }
    // last-CTA BN finalize (threadFenceReduction pattern)
    __threadfence();
    __syncthreads();
    if (tid == 0) {
        int c = atomicAdd(&g_cnt[LAYER], 1);
        isLast = (c == (int)gridDim.x - 1);
    }
    __syncthreads();
    if (isLast) {
        if (tid < N) {
            double mean = g_sum[tid]   * (1.0 / (double)NTOT);
            double var  = g_sqsum[tid] * (1.0 / (double)NTOT) - mean*mean;
            float sc = gamma[tid] * (float)(1.0 / sqrt(var + 1e-5));
            g_scale[LAYER][tid] = sc;
            g_shift[LAYER][tid] = __fmaf_rn(-(float)mean, sc, beta[tid]);
            g_sum[tid] = 0.0; g_sqsum[tid] = 0.0;
        }
        if (tid == 0) g_cnt[LAYER] = 0;
        __threadfence();
    }
}

// -------- final affine+relu on pooled max/min --------
__global__ void pool_apply_kernel(float* __restrict__ out) {
    int idx = blockIdx.x * 256 + threadIdx.x;
    int o = idx & 127;
    float sc = g_scale[2][o], sh = g_shift[2][o];
    float vmx = __fmaf_rn(sc, g_mx[idx], sh);
    float vmn = __fmaf_rn(sc, g_mn[idx], sh);
    out[idx] = fmaxf(fmaxf(vmx, vmn), 0.f);
}

extern "C" void kernel_launch(void* const* d_in, const int* in_sizes, int n_in,
                              void* d_out, int out_size) {
    const float* xyz  = (const float*)d_in[0];
    const float* feat = (const float*)d_in[1];
    const int*   sidx = (const int*)d_in[2];
    const float *w1=(const float*)d_in[3],
                *g1=(const float*)d_in[5],  *t1=(const float*)d_in[6];
    const float *w2=(const float*)d_in[7],
                *g2=(const float*)d_in[9],  *t2=(const float*)d_in[10];
    const float *w3=(const float*)d_in[11],
                *g3=(const float*)d_in[13], *t3=(const float*)d_in[14];
    float* out      = (float*)d_out;
    float* new_xyz  = out;
    float* new_feat = out + NQ*3;

    float* bufA; cudaGetSymbolAddress((void**)&bufA, g_bufA);
    float* bufB; cudaGetSymbolAddress((void**)&bufB, g_bufB);

    const int SK = 3*P1*4;                             // 98304 -> 2 CTAs/SM
    const int S1 = (256 + 128) * (80+8) * 2 + 64*8;    // 68096
    const int S2 = (256 + 128) * (64+8) * 2 + 64*8;    // 55808
    const int S3 = (256 + 256) * (64+8) * 2 + 128*8;   // 74752
    cudaFuncSetAttribute(knn_kernel, cudaFuncAttributeMaxDynamicSharedMemorySize, SK);
    cudaFuncSetAttribute(gemm_kernel<80,67,64,0,0,0>,  cudaFuncAttributeMaxDynamicSharedMemorySize, S1);
    cudaFuncSetAttribute(gemm_kernel<64,64,64,1,0,1>,  cudaFuncAttributeMaxDynamicSharedMemorySize, S2);
    cudaFuncSetAttribute(gemm_kernel<64,64,128,1,1,2>, cudaFuncAttributeMaxDynamicSharedMemorySize, S3);

    knn_kernel<<<NQ/32, 1024, SK>>>(xyz, sidx, new_xyz);
    gemm_kernel<80,67,64,0,0,0><<<NTOT/128, 256, S1>>>(feat, xyz, new_xyz, nullptr, w1, bufA, g1, t1);
    gemm_kernel<64,64,64,1,0,1><<<NTOT/128, 256, S2>>>(nullptr, nullptr, nullptr, bufA, w2, bufB, g2, t2);
    gemm_kernel<64,64,128,1,1,2><<<NTOT/128, 256, S3>>>(nullptr, nullptr, nullptr, bufB, w3, nullptr, g3, t3);
    pool_apply_kernel<<<(NQ*128)/256, 256>>>(new_feat);
}

// round 14
// speedup vs baseline: 1.0407x; 1.0407x over previous
#include <cuda_runtime.h>
#include <cuda_bf16.h>
#include <cfloat>
#include <math.h>
#include <cstdint>

#define BSZ 8
#define P1  8192
#define P2  2048
#define KNB 32
#define NQ  16384
#define NTOT 524288ull

typedef unsigned long long ull;

__device__ int    g_nn[NQ*KNB];
__device__ float4 g_sorted[BSZ*P1];   // z-bin-sorted points, w = orig idx bits
__device__ float  g_bufA[NTOT*64];    // y1 [n][64]
__device__ float  g_bufB[NTOT*64];    // y2 [n][64]
__device__ float  g_mx[NQ*128];
__device__ float  g_mn[NQ*128];
__device__ double g_sum[128];
__device__ double g_sqsum[128];
__device__ float  g_scale[3][128];
__device__ float  g_shift[3][128];

static __device__ __forceinline__ uint32_t smem_u32(const void* p) {
    uint32_t a; asm("{ .reg .u64 t; cvta.to.shared.u64 t, %1; cvt.u32.u64 %0, t; }" : "=r"(a) : "l"(p));
    return a;
}
static __device__ __forceinline__ void ldsm4(uint32_t* r, uint32_t a) {
    asm volatile("ldmatrix.sync.aligned.m8n8.x4.shared.b16 {%0,%1,%2,%3}, [%4];"
        : "=r"(r[0]), "=r"(r[1]), "=r"(r[2]), "=r"(r[3]) : "r"(a));
}
static __device__ __forceinline__ void ldsm2(uint32_t* r, uint32_t a) {
    asm volatile("ldmatrix.sync.aligned.m8n8.x2.shared.b16 {%0,%1}, [%2];"
        : "=r"(r[0]), "=r"(r[1]) : "r"(a));
}
static __device__ __forceinline__ void mma16816(float* d, const uint32_t* a, const uint32_t* b) {
    asm volatile("mma.sync.aligned.m16n8k16.row.col.f32.bf16.bf16.f32 "
        "{%0,%1,%2,%3},{%4,%5,%6,%7},{%8,%9},{%0,%1,%2,%3};"
        : "+f"(d[0]), "+f"(d[1]), "+f"(d[2]), "+f"(d[3])
        : "r"(a[0]), "r"(a[1]), "r"(a[2]), "r"(a[3]), "r"(b[0]), "r"(b[1]));
}
static __device__ __forceinline__ void split1(float v, __nv_bfloat16 &h, __nv_bfloat16 &l) {
    h = __float2bfloat16_rn(v);
    l = __float2bfloat16_rn(v - __bfloat162float(h));
}
static __device__ __forceinline__ void split4(float4 v, uint2 &H, uint2 &L) {
    __nv_bfloat16 hx, hy, hz, hw, lx, ly, lz, lw;
    split1(v.x, hx, lx); split1(v.y, hy, ly);
    split1(v.z, hz, lz); split1(v.w, hw, lw);
    H.x = (uint32_t)__bfloat16_as_ushort(hx) | ((uint32_t)__bfloat16_as_ushort(hy) << 16);
    H.y = (uint32_t)__bfloat16_as_ushort(hz) | ((uint32_t)__bfloat16_as_ushort(hw) << 16);
    L.x = (uint32_t)__bfloat16_as_ushort(lx) | ((uint32_t)__bfloat16_as_ushort(ly) << 16);
    L.y = (uint32_t)__bfloat16_as_ushort(lz) | ((uint32_t)__bfloat16_as_ushort(lw) << 16);
}

// -------- counting sort by z, 1024 bins, one block per batch --------
__global__ __launch_bounds__(1024) void zsort_kernel(const float* __restrict__ xyz) {
    __shared__ int hist[1024];
    __shared__ int wsum[32];
    __shared__ int offs[1024];
    const int tid = threadIdx.x, w = tid >> 5, lane = tid & 31;
    const int b = blockIdx.x;
    const float* base = xyz + (size_t)b*P1*3;

    hist[tid] = 0;
    __syncthreads();
    #pragma unroll
    for (int it = 0; it < 8; it++) {
        int j = tid + 1024*it;
        float z = base[3*j+2];
        int bin = min(max((int)((z + 4.f) * 128.f), 0), 1023);
        atomicAdd(&hist[bin], 1);
    }
    __syncthreads();
    int v = hist[tid], s = v;
    #pragma unroll
    for (int off = 1; off < 32; off <<= 1) {
        int t = __shfl_up_sync(0xffffffffu, s, off);
        if (lane >= off) s += t;
    }
    if (lane == 31) wsum[w] = s;
    __syncthreads();
    if (w == 0) {
        int ws = wsum[lane];
        #pragma unroll
        for (int off = 1; off < 32; off <<= 1) {
            int t = __shfl_up_sync(0xffffffffu, ws, off);
            if (lane >= off) ws += t;
        }
        wsum[lane] = ws;
    }
    __syncthreads();
    offs[tid] = ((w == 0) ? 0 : wsum[w-1]) + s - v;   // exclusive prefix
    __syncthreads();
    #pragma unroll
    for (int it = 0; it < 8; it++) {
        int j = tid + 1024*it;
        float x = base[3*j], y = base[3*j+1], z = base[3*j+2];
        int bin = min(max((int)((z + 4.f) * 128.f), 0), 1023);
        int pos = atomicAdd(&offs[bin], 1);
        g_sorted[(size_t)b*P1 + pos] = make_float4(x, y, z, __int_as_float(j));
    }
}

// -------- KNN: warp/query, outward z-scan, amortized coarse prune --------
__global__ __launch_bounds__(1024) void knn_kernel(const float* __restrict__ xyz,
                           const int*   __restrict__ sidx,
                           float*       __restrict__ out_xyz) {
    extern __shared__ float4 pts[];                 // 8192*16B = 128KB
    const int tid = threadIdx.x, w = tid >> 5, lane = tid & 31;
    const int qbase = blockIdx.x * 32;
    const int b = qbase / P2;

    const float4* sp = g_sorted + (size_t)b*P1;
    for (int j = tid; j < P1; j += 1024) pts[j] = sp[j];
    __syncthreads();

    const int q  = qbase + w;
    const int si = sidx[q];
    const float* bx = xyz + (size_t)b*P1*3;
    const float qx = bx[3*si], qy = bx[3*si+1], qz = bx[3*si+2];
    const float rA = __fadd_rn(__fadd_rn(__fmul_rn(qx,qx), __fmul_rn(qy,qy)), __fmul_rn(qz,qz));
    if (lane < 3) out_xyz[(size_t)q*3 + lane] = (lane == 0) ? qx : (lane == 1 ? qy : qz);

    // approximate start chunk: binary search z (bin-monotone; exactness not required)
    int lp = 0, hp = P1 - 1;
    while (lp < hp) { int m = (lp + hp) >> 1; if (pts[m].z < qz) lp = m + 1; else hp = m; }
    int c0 = min(lp >> 5, 255);

    float best_d = FLT_MAX; int best_i = 0;   // ascending (d,i) across lanes
    float thr = FLT_MAX;
    int lo = c0, hi = c0 + 1;
    bool doneL = false, doneR = (hi > 255);
    bool sideL = true;
    int it = 0;

    while (!doneL || !doneR) {
        int c;
        if (!doneL && (sideL || doneR)) { c = lo; lo--; if (lo < 0) doneL = true; }
        else                            { c = hi; hi++; if (hi > 255) doneR = true; }
        sideL = !sideL;

        float4 pt = pts[(c<<5) + lane];
        int pidx = __float_as_int(pt.w);
        float r2  = __fadd_rn(__fadd_rn(__fmul_rn(pt.x,pt.x), __fmul_rn(pt.y,pt.y)), __fmul_rn(pt.z,pt.z));
        float dot = __fmaf_rn(qz, pt.z, __fmaf_rn(qy, pt.y, __fmul_rn(qx, pt.x)));
        float d   = __fadd_rn(__fsub_rn(rA, __fmul_rn(2.f, dot)), r2);
        unsigned m = __ballot_sync(0xffffffffu, d < thr);
        while (m) {
            int src = __ffs(m) - 1; m &= m - 1;
            float dc = __shfl_sync(0xffffffffu, d, src);
            int   ic = __shfl_sync(0xffffffffu, pidx, src);
            unsigned bal = __ballot_sync(0xffffffffu, dc < best_d);
            if (bal) {
                int pos  = __ffs(bal) - 1;
                float ud = __shfl_up_sync(0xffffffffu, best_d, 1);
                int   ui = __shfl_up_sync(0xffffffffu, best_i, 1);
                if (lane > pos)       { best_d = ud; best_i = ui; }
                else if (lane == pos) { best_d = dc; best_i = ic; }
            }
        }
        thr = __shfl_sync(0xffffffffu, best_d, 31);

        if (((++it) & 3) == 0) {
            if (!doneL) {   // chunks <= lo: z <= upper bin edge of element lo*32+31
                float z = pts[(lo<<5) + 31].z;
                float bin = floorf(__fmaf_rn(z, 128.f, 512.f));
                if (bin < 1023.f) {
                    float gap = qz - __fmaf_rn(bin + 1.f, 0.0078125f, -4.f);
                    if (gap > 0.f && gap*gap > thr) doneL = true;
                }
            }
            if (!doneR) {   // chunks >= hi: z >= lower bin edge of element hi*32
                float z = pts[hi<<5].z;
                float bin = floorf(__fmaf_rn(z, 128.f, 512.f));
                if (bin > 0.f) {
                    float gap = __fmaf_rn(bin, 0.0078125f, -4.f) - qz;
                    if (gap > 0.f && gap*gap > thr) doneR = true;
                }
            }
        }
    }
    g_nn[(size_t)q*KNB + lane] = best_i;
}

// -------- GEMM layer via mma.sync bf16 (3-term split), M=128/CTA (exact R8 body) --------
template<int KPAD, int CIN, int N, int MODE, int POOL>
__global__ __launch_bounds__(256) void gemm_kernel(
        const float* __restrict__ feat, const float* __restrict__ xyz,
        const float* __restrict__ qxyz, const float* __restrict__ y_in,
        const float* __restrict__ W,    float* __restrict__ y_out, int prev)
{
    extern __shared__ char smem[];
    constexpr int ST = KPAD + 8;
    constexpr int OFF_AH = 0;
    constexpr int OFF_AL = 128*ST*2;
    constexpr int OFF_BH = 2*OFF_AL;
    constexpr int OFF_BL = OFF_BH + N*ST*2;
    constexpr int OFF_S  = OFF_BL + N*ST*2;
    float* ssum = (float*)(smem + OFF_S);
    float* ssq  = ssum + N;
    const uint32_t sb = smem_u32(smem);
    const int tid = threadIdx.x;
    const int n0  = blockIdx.x * 128;
    const int cq  = tid & 15, rs = tid >> 4;

    if (tid < N) { ssum[tid] = 0.f; ssq[tid] = 0.f; }

    if (MODE == 0) {
        uint4 z = make_uint4(0,0,0,0);
        if (tid < 128 + N) {
            int isA = tid < 128;
            int row = isA ? tid : tid - 128;
            char* base = smem + (isA ? OFF_AH : OFF_BH) + row*ST*2 + 128;
            char* basl = smem + (isA ? OFF_AL : OFF_BL) + row*ST*2 + 128;
            *(uint4*)(base) = z;      *(uint4*)(base + 16) = z;
            *(uint4*)(basl) = z;      *(uint4*)(basl + 16) = z;
        }
        #pragma unroll
        for (int it = 0; it < 8; it++) {
            int row = rs + 16*it;
            int n   = n0 + row;
            int b   = n >> 16;
            int nn  = g_nn[n];
            float4 f = *(const float4*)(feat + (size_t)(b*P1 + nn)*64 + 4*cq);
            uint2 H, L; split4(f, H, L);
            *(uint2*)(smem + OFF_AH + row*ST*2 + 8*cq) = H;
            *(uint2*)(smem + OFF_AL + row*ST*2 + 8*cq) = L;
            if (cq == 0) {
                int q = n >> 5;
                const float* nx = xyz  + (size_t)(b*P1 + nn)*3;
                const float* qp = qxyz + (size_t)q*3;
                #pragma unroll
                for (int j = 0; j < 3; j++) {
                    __nv_bfloat16 h, l; split1(__fsub_rn(nx[j], qp[j]), h, l);
                    *(__nv_bfloat16*)(smem + OFF_AH + row*ST*2 + 128 + 2*j) = h;
                    *(__nv_bfloat16*)(smem + OFF_AL + row*ST*2 + 128 + 2*j) = l;
                }
            }
        }
        #pragma unroll
        for (int it = 0; it < N/16; it++) {
            int o = rs + 16*it;
            const float* wr = W + (size_t)o*CIN;
            float4 w4 = make_float4(wr[4*cq], wr[4*cq+1], wr[4*cq+2], wr[4*cq+3]);
            uint2 H, L; split4(w4, H, L);
            *(uint2*)(smem + OFF_BH + o*ST*2 + 8*cq) = H;
            *(uint2*)(smem + OFF_BL + o*ST*2 + 8*cq) = L;
            if (cq == 0) {
                #pragma unroll
                for (int j = 0; j < 3; j++) {
                    __nv_bfloat16 h, l; split1(wr[64 + j], h, l);
                    *(__nv_bfloat16*)(smem + OFF_BH + o*ST*2 + 128 + 2*j) = h;
                    *(__nv_bfloat16*)(smem + OFF_BL + o*ST*2 + 128 + 2*j) = l;
                }
            }
        }
    } else {
        const float4 sc4 = *(const float4*)(g_scale[prev] + 4*cq);
        const float4 sh4 = *(const float4*)(g_shift[prev] + 4*cq);
        #pragma unroll
        for (int it = 0; it < 8; it++) {
            int row = rs + 16*it;
            float4 v = *(const float4*)(y_in + (size_t)(n0 + row)*64 + 4*cq);
            v.x = fmaxf(__fmaf_rn(sc4.x, v.x, sh4.x), 0.f);
            v.y = fmaxf(__fmaf_rn(sc4.y, v.y, sh4.y), 0.f);
            v.z = fmaxf(__fmaf_rn(sc4.z, v.z, sh4.z), 0.f);
            v.w = fmaxf(__fmaf_rn(sc4.w, v.w, sh4.w), 0.f);
            uint2 H, L; split4(v, H, L);
            *(uint2*)(smem + OFF_AH + row*ST*2 + 8*cq) = H;
            *(uint2*)(smem + OFF_AL + row*ST*2 + 8*cq) = L;
        }
        #pragma unroll
        for (int it = 0; it < N/16; it++) {
            int o = rs + 16*it;
            float4 w4 = *(const float4*)(W + (size_t)o*64 + 4*cq);
            uint2 H, L; split4(w4, H, L);
            *(uint2*)(smem + OFF_BH + o*ST*2 + 8*cq) = H;
            *(uint2*)(smem + OFF_BL + o*ST*2 + 8*cq) = L;
        }
    }
    __syncthreads();

    const int w = tid >> 5, lane = tid & 31;
    const int mw = w & 3, nw = w >> 2;
    constexpr int NB = N/16;

    float acc[2][NB][4];
    #pragma unroll
    for (int mh = 0; mh < 2; mh++)
        #pragma unroll
        for (int nb = 0; nb < NB; nb++)
            #pragma unroll
            for (int j = 0; j < 4; j++) acc[mh][nb][j] = 0.f;

    const uint32_t aoff = ((mw*32 + (lane & 15))*ST + (lane >> 4)*8) * 2;
    const uint32_t boff = ((nw*(N/2) + (lane & 7))*ST + ((lane >> 3) & 1)*8) * 2;

    #pragma unroll
    for (int kk = 0; kk < KPAD/16; kk++) {
        uint32_t ah[2][4], al[2][4];
        #pragma unroll
        for (int mh = 0; mh < 2; mh++) {
            ldsm4(ah[mh], sb + OFF_AH + aoff + (mh*16*ST + kk*16)*2);
            ldsm4(al[mh], sb + OFF_AL + aoff + (mh*16*ST + kk*16)*2);
        }
        #pragma unroll
        for (int nb = 0; nb < NB; nb++) {
            uint32_t bh[2], bl[2];
            ldsm2(bh, sb + OFF_BH + boff + (nb*8*ST + kk*16)*2);
            ldsm2(bl, sb + OFF_BL + boff + (nb*8*ST + kk*16)*2);
            #pragma unroll
            for (int mh = 0; mh < 2; mh++) {
                mma16816(acc[mh][nb], ah[mh], bh);
                mma16816(acc[mh][nb], ah[mh], bl);
                mma16816(acc[mh][nb], al[mh], bh);
            }
        }
    }

    const int g = lane >> 2, t = lane & 3;
    #pragma unroll
    for (int nb = 0; nb < NB; nb++) {
        float s0 = acc[0][nb][0] + acc[0][nb][2] + acc[1][nb][0] + acc[1][nb][2];
        float s1 = acc[0][nb][1] + acc[0][nb][3] + acc[1][nb][1] + acc[1][nb][3];
        float q0 = acc[0][nb][0]*acc[0][nb][0] + acc[0][nb][2]*acc[0][nb][2]
                 + acc[1][nb][0]*acc[1][nb][0] + acc[1][nb][2]*acc[1][nb][2];
        float q1 = acc[0][nb][1]*acc[0][nb][1] + acc[0][nb][3]*acc[0][nb][3]
                 + acc[1][nb][1]*acc[1][nb][1] + acc[1][nb][3]*acc[1][nb][3];
        float mx0, mn0, mx1, mn1;
        if (POOL) {
            mx0 = fmaxf(fmaxf(acc[0][nb][0], acc[0][nb][2]), fmaxf(acc[1][nb][0], acc[1][nb][2]));
            mn0 = fminf(fminf(acc[0][nb][0], acc[0][nb][2]), fminf(acc[1][nb][0], acc[1][nb][2]));
            mx1 = fmaxf(fmaxf(acc[0][nb][1], acc[0][nb][3]), fmaxf(acc[1][nb][1], acc[1][nb][3]));
            mn1 = fminf(fminf(acc[0][nb][1], acc[0][nb][3]), fminf(acc[1][nb][1], acc[1][nb][3]));
        }
        #pragma unroll
        for (int off = 4; off < 32; off <<= 1) {
            s0 += __shfl_xor_sync(0xffffffffu, s0, off);
            s1 += __shfl_xor_sync(0xffffffffu, s1, off);
            q0 += __shfl_xor_sync(0xffffffffu, q0, off);
            q1 += __shfl_xor_sync(0xffffffffu, q1, off);
            if (POOL) {
                mx0 = fmaxf(mx0, __shfl_xor_sync(0xffffffffu, mx0, off));
                mn0 = fminf(mn0, __shfl_xor_sync(0xffffffffu, mn0, off));
                mx1 = fmaxf(mx1, __shfl_xor_sync(0xffffffffu, mx1, off));
                mn1 = fminf(mn1, __shfl_xor_sync(0xffffffffu, mn1, off));
            }
        }
        if (g == 0) {
            int col = nw*(N/2) + nb*8 + 2*t;
            atomicAdd(&ssum[col],   s0); atomicAdd(&ssum[col+1], s1);
            atomicAdd(&ssq[col],    q0); atomicAdd(&ssq[col+1],  q1);
            if (POOL) {
                int q = blockIdx.x*4 + mw;
                g_mx[(size_t)q*128 + col]   = mx0;  g_mn[(size_t)q*128 + col]   = mn0;
                g_mx[(size_t)q*128 + col+1] = mx1;  g_mn[(size_t)q*128 + col+1] = mn1;
            }
        }
    }

    if (!POOL) {
        #pragma unroll
        for (int mh = 0; mh < 2; mh++) {
            #pragma unroll
            for (int nb = 0; nb < NB; nb++) {
                int row = n0 + mw*32 + mh*16 + g;
                int col = nw*(N/2) + nb*8 + 2*t;
                *(float2*)(y_out + (size_t)row*N + col)       = make_float2(acc[mh][nb][0], acc[mh][nb][1]);
                *(float2*)(y_out + (size_t)(row + 8)*N + col) = make_float2(acc[mh][nb][2], acc[mh][nb][3]);
            }
        }
    }

    __syncthreads();
    if (tid < N) {
        atomicAdd(&g_sum[tid],   (double)ssum[tid]);
        atomicAdd(&g_sqsum[tid], (double)ssq[tid]);
    }
}

// -------- BN finalize --------
__global__ void finalize_kernel(const float* __restrict__ gamma,
                                const float* __restrict__ beta,
                                int layer) {
    int o = threadIdx.x;
    double mean = g_sum[o]   * (1.0 / (double)NTOT);
    double var  = g_sqsum[o] * (1.0 / (double)NTOT) - mean*mean;
    float sc = gamma[o] * (float)(1.0 / sqrt(var + 1e-5));
    g_scale[layer][o] = sc;
    g_shift[layer][o] = __fmaf_rn(-(float)mean, sc, beta[o]);
    g_sum[o] = 0.0; g_sqsum[o] = 0.0;
}

// -------- final affine+relu on pooled max/min --------
__global__ void pool_apply_kernel(float* __restrict__ out) {
    int idx = blockIdx.x * 256 + threadIdx.x;
    int o = idx & 127;
    float sc = g_scale[2][o], sh = g_shift[2][o];
    float vmx = __fmaf_rn(sc, g_mx[idx], sh);
    float vmn = __fmaf_rn(sc, g_mn[idx], sh);
    out[idx] = fmaxf(fmaxf(vmx, vmn), 0.f);
}

extern "C" void kernel_launch(void* const* d_in, const int* in_sizes, int n_in,
                              void* d_out, int out_size) {
    const float* xyz  = (const float*)d_in[0];
    const float* feat = (const float*)d_in[1];
    const int*   sidx = (const int*)d_in[2];
    const float *w1=(const float*)d_in[3],
                *g1=(const float*)d_in[5],  *t1=(const float*)d_in[6];
    const float *w2=(const float*)d_in[7],
                *g2=(const float*)d_in[9],  *t2=(const float*)d_in[10];
    const float *w3=(const float*)d_in[11],
                *g3=(const float*)d_in[13], *t3=(const float*)d_in[14];
    float* out      = (float*)d_out;
    float* new_xyz  = out;
    float* new_feat = out + NQ*3;

    float* bufA; cudaGetSymbolAddress((void**)&bufA, g_bufA);
    float* bufB; cudaGetSymbolAddress((void**)&bufB, g_bufB);

    const int S1 = (256 + 128) * (80+8) * 2 + 64*8;    // 68096
    const int S2 = (256 + 128) * (64+8) * 2 + 64*8;    // 55808
    const int S3 = (256 + 256) * (64+8) * 2 + 128*8;   // 74752
    cudaFuncSetAttribute(knn_kernel, cudaFuncAttributeMaxDynamicSharedMemorySize, 131072);
    cudaFuncSetAttribute(gemm_kernel<80,67,64,0,0>,  cudaFuncAttributeMaxDynamicSharedMemorySize, S1);
    cudaFuncSetAttribute(gemm_kernel<64,64,64,1,0>,  cudaFuncAttributeMaxDynamicSharedMemorySize, S2);
    cudaFuncSetAttribute(gemm_kernel<64,64,128,1,1>, cudaFuncAttributeMaxDynamicSharedMemorySize, S3);

    zsort_kernel<<<BSZ, 1024>>>(xyz);
    knn_kernel<<<NQ/32, 1024, 131072>>>(xyz, sidx, new_xyz);
    gemm_kernel<80,67,64,0,0><<<NTOT/128, 256, S1>>>(feat, xyz, new_xyz, nullptr, w1, bufA, 0);
    finalize_kernel<<<1,64>>>(g1, t1, 0);
    gemm_kernel<64,64,64,1,0><<<NTOT/128, 256, S2>>>(nullptr, nullptr, nullptr, bufA, w2, bufB, 0);
    finalize_kernel<<<1,64>>>(g2, t2, 1);
    gemm_kernel<64,64,128,1,1><<<NTOT/128, 256, S3>>>(nullptr, nullptr, nullptr, bufB, w3, nullptr, 1);
    finalize_kernel<<<1,128>>>(g3, t3, 2);
    pool_apply_kernel<<<(NQ*128)/256, 256>>>(new_feat);
}

// round 15
// speedup vs baseline: 1.0522x; 1.0111x over previous
#include <cuda_runtime.h>
#include <cuda_bf16.h>
#include <cfloat>
#include <math.h>
#include <cstdint>

#define BSZ 8
#define P1  8192
#define P2  2048
#define KNB 32
#define NQ  16384
#define NTOT 524288ull

typedef unsigned long long ull;

__device__ int    g_nn[NQ*KNB];
__device__ float  g_bufA[NTOT*64];    // y1 [n][64]
__device__ float  g_bufB[NTOT*64];    // y2 [n][64]
__device__ float  g_mx[NQ*128];
__device__ float  g_mn[NQ*128];
__device__ double g_sum[128];
__device__ double g_sqsum[128];
__device__ float  g_scale[3][128];
__device__ float  g_shift[3][128];
__device__ int    g_dummy;

static __device__ __forceinline__ uint32_t smem_u32(const void* p) {
    uint32_t a; asm("{ .reg .u64 t; cvta.to.shared.u64 t, %1; cvt.u32.u64 %0, t; }" : "=r"(a) : "l"(p));
    return a;
}
static __device__ __forceinline__ void ldsm4(uint32_t* r, uint32_t a) {
    asm volatile("ldmatrix.sync.aligned.m8n8.x4.shared.b16 {%0,%1,%2,%3}, [%4];"
        : "=r"(r[0]), "=r"(r[1]), "=r"(r[2]), "=r"(r[3]) : "r"(a));
}
static __device__ __forceinline__ void ldsm2(uint32_t* r, uint32_t a) {
    asm volatile("ldmatrix.sync.aligned.m8n8.x2.shared.b16 {%0,%1}, [%2];"
        : "=r"(r[0]), "=r"(r[1]) : "r"(a));
}
static __device__ __forceinline__ void mma16816(float* d, const uint32_t* a, const uint32_t* b) {
    asm volatile("mma.sync.aligned.m16n8k16.row.col.f32.bf16.bf16.f32 "
        "{%0,%1,%2,%3},{%4,%5,%6,%7},{%8,%9},{%0,%1,%2,%3};"
        : "+f"(d[0]), "+f"(d[1]), "+f"(d[2]), "+f"(d[3])
        : "r"(a[0]), "r"(a[1]), "r"(a[2]), "r"(a[3]), "r"(b[0]), "r"(b[1]));
}
static __device__ __forceinline__ void split1(float v, __nv_bfloat16 &h, __nv_bfloat16 &l) {
    h = __float2bfloat16_rn(v);
    l = __float2bfloat16_rn(v - __bfloat162float(h));
}
static __device__ __forceinline__ void split4(float4 v, uint2 &H, uint2 &L) {
    __nv_bfloat16 hx, hy, hz, hw, lx, ly, lz, lw;
    split1(v.x, hx, lx); split1(v.y, hy, ly);
    split1(v.z, hz, lz); split1(v.w, hw, lw);
    H.x = (uint32_t)__bfloat16_as_ushort(hx) | ((uint32_t)__bfloat16_as_ushort(hy) << 16);
    H.y = (uint32_t)__bfloat16_as_ushort(hz) | ((uint32_t)__bfloat16_as_ushort(hw) << 16);
    L.x = (uint32_t)__bfloat16_as_ushort(lx) | ((uint32_t)__bfloat16_as_ushort(ly) << 16);
    L.y = (uint32_t)__bfloat16_as_ushort(lz) | ((uint32_t)__bfloat16_as_ushort(lw) << 16);
}
// order-preserving key for IEEE floats (handles tiny negatives from rounding)
static __device__ __forceinline__ uint32_t fkey(float d) {
    uint32_t b = __float_as_uint(d);
    return b ^ ((b & 0x80000000u) ? 0xFFFFFFFFu : 0x80000000u);
}

// -------- dummy no-op kernels (shift ncu capture slot onto knn_kernel) --------
__global__ void nop_kernel(int v) { if (threadIdx.x > 1024) g_dummy = v; }

// -------- KNN: warp per query; unsorted top-32 buffer + redux-max threshold --------
__global__ __launch_bounds__(1024) void knn_kernel(const float* __restrict__ xyz,
                           const int*   __restrict__ sidx,
                           float*       __restrict__ out_xyz) {
    extern __shared__ float4 pts[];                 // 8192*16B = 128KB
    const int tid  = threadIdx.x;
    const int warp = tid >> 5, lane = tid & 31;
    const int qbase = blockIdx.x * 32;
    const int b = qbase / P2;
    const float* bx = xyz + (size_t)b * P1 * 3;

    for (int j = tid; j < P1; j += 1024) {
        float x = bx[3*j], y = bx[3*j+1], z = bx[3*j+2];
        float r2 = __fadd_rn(__fadd_rn(__fmul_rn(x,x), __fmul_rn(y,y)), __fmul_rn(z,z));
        pts[j] = make_float4(x, y, z, r2);
    }
    __syncthreads();

    const int q  = qbase + warp;
    const int si = sidx[q];
    const float qx = bx[3*si], qy = bx[3*si+1], qz = bx[3*si+2];
    const float rA = __fadd_rn(__fadd_rn(__fmul_rn(qx,qx), __fmul_rn(qy,qy)), __fmul_rn(qz,qz));
    if (lane < 3) out_xyz[(size_t)q*3 + lane] = (lane == 0) ? qx : (lane == 1 ? qy : qz);

    uint32_t bkey = 0xFFFFFFFFu; int bidx = 0;     // unsorted per-lane slot
    uint32_t thr  = 0xFFFFFFFFu;                   // current max key in buffer

    float4 pt = pts[lane];
    for (int j0 = 0; j0 < P1; j0 += 32) {
        float4 nxt = pts[((j0 + 32) & (P1 - 1)) + lane];   // prefetch (wraps on last)
        float dot = __fmaf_rn(qz, pt.z, __fmaf_rn(qy, pt.y, __fmul_rn(qx, pt.x)));
        float d   = __fadd_rn(__fsub_rn(rA, __fmul_rn(2.f, dot)), pt.w);
        uint32_t key = fkey(d);
        unsigned m = __ballot_sync(0xffffffffu, key < thr);
        while (m) {
            int src = __ffs(m) - 1; m &= m - 1;
            uint32_t kc = __shfl_sync(0xffffffffu, key, src);
            if (kc < thr) {                                   // warp-uniform
                unsigned bm = __ballot_sync(0xffffffffu, bkey == thr);
                int ev = 31 - __clz(bm);
                if (lane == ev) { bkey = kc; bidx = j0 + src; }
                thr = __reduce_max_sync(0xffffffffu, bkey);
            }
        }
        pt = nxt;
    }
    g_nn[(size_t)q*KNB + lane] = bidx;   // order within query irrelevant (BN/pool invariant)
}

// -------- GEMM layer via mma.sync bf16 (3-term split), M=128/CTA (exact R8 body) --------
template<int KPAD, int CIN, int N, int MODE, int POOL>
__global__ __launch_bounds__(256) void gemm_kernel(
        const float* __restrict__ feat, const float* __restrict__ xyz,
        const float* __restrict__ qxyz, const float* __restrict__ y_in,
        const float* __restrict__ W,    float* __restrict__ y_out, int prev)
{
    extern __shared__ char smem[];
    constexpr int ST = KPAD + 8;
    constexpr int OFF_AH = 0;
    constexpr int OFF_AL = 128*ST*2;
    constexpr int OFF_BH = 2*OFF_AL;
    constexpr int OFF_BL = OFF_BH + N*ST*2;
    constexpr int OFF_S  = OFF_BL + N*ST*2;
    float* ssum = (float*)(smem + OFF_S);
    float* ssq  = ssum + N;
    const uint32_t sb = smem_u32(smem);
    const int tid = threadIdx.x;
    const int n0  = blockIdx.x * 128;
    const int cq  = tid & 15, rs = tid >> 4;

    if (tid < N) { ssum[tid] = 0.f; ssq[tid] = 0.f; }

    if (MODE == 0) {
        uint4 z = make_uint4(0,0,0,0);
        if (tid < 128 + N) {
            int isA = tid < 128;
            int row = isA ? tid : tid - 128;
            char* base = smem + (isA ? OFF_AH : OFF_BH) + row*ST*2 + 128;
            char* basl = smem + (isA ? OFF_AL : OFF_BL) + row*ST*2 + 128;
            *(uint4*)(base) = z;      *(uint4*)(base + 16) = z;
            *(uint4*)(basl) = z;      *(uint4*)(basl + 16) = z;
        }
        #pragma unroll
        for (int it = 0; it < 8; it++) {
            int row = rs + 16*it;
            int n   = n0 + row;
            int b   = n >> 16;
            int nn  = g_nn[n];
            float4 f = *(const float4*)(feat + (size_t)(b*P1 + nn)*64 + 4*cq);
            uint2 H, L; split4(f, H, L);
            *(uint2*)(smem + OFF_AH + row*ST*2 + 8*cq) = H;
            *(uint2*)(smem + OFF_AL + row*ST*2 + 8*cq) = L;
            if (cq == 0) {
                int q = n >> 5;
                const float* nx = xyz  + (size_t)(b*P1 + nn)*3;
                const float* qp = qxyz + (size_t)q*3;
                #pragma unroll
                for (int j = 0; j < 3; j++) {
                    __nv_bfloat16 h, l; split1(__fsub_rn(nx[j], qp[j]), h, l);
                    *(__nv_bfloat16*)(smem + OFF_AH + row*ST*2 + 128 + 2*j) = h;
                    *(__nv_bfloat16*)(smem + OFF_AL + row*ST*2 + 128 + 2*j) = l;
                }
            }
        }
        #pragma unroll
        for (int it = 0; it < N/16; it++) {
            int o = rs + 16*it;
            const float* wr = W + (size_t)o*CIN;
            float4 w4 = make_float4(wr[4*cq], wr[4*cq+1], wr[4*cq+2], wr[4*cq+3]);
            uint2 H, L; split4(w4, H, L);
            *(uint2*)(smem + OFF_BH + o*ST*2 + 8*cq) = H;
            *(uint2*)(smem + OFF_BL + o*ST*2 + 8*cq) = L;
            if (cq == 0) {
                #pragma unroll
                for (int j = 0; j < 3; j++) {
                    __nv_bfloat16 h, l; split1(wr[64 + j], h, l);
                    *(__nv_bfloat16*)(smem + OFF_BH + o*ST*2 + 128 + 2*j) = h;
                    *(__nv_bfloat16*)(smem + OFF_BL + o*ST*2 + 128 + 2*j) = l;
                }
            }
        }
    } else {
        const float4 sc4 = *(const float4*)(g_scale[prev] + 4*cq);
        const float4 sh4 = *(const float4*)(g_shift[prev] + 4*cq);
        #pragma unroll
        for (int it = 0; it < 8; it++) {
            int row = rs + 16*it;
            float4 v = *(const float4*)(y_in + (size_t)(n0 + row)*64 + 4*cq);
            v.x = fmaxf(__fmaf_rn(sc4.x, v.x, sh4.x), 0.f);
            v.y = fmaxf(__fmaf_rn(sc4.y, v.y, sh4.y), 0.f);
            v.z = fmaxf(__fmaf_rn(sc4.z, v.z, sh4.z), 0.f);
            v.w = fmaxf(__fmaf_rn(sc4.w, v.w, sh4.w), 0.f);
            uint2 H, L; split4(v, H, L);
            *(uint2*)(smem + OFF_AH + row*ST*2 + 8*cq) = H;
            *(uint2*)(smem + OFF_AL + row*ST*2 + 8*cq) = L;
        }
        #pragma unroll
        for (int it = 0; it < N/16; it++) {
            int o = rs + 16*it;
            float4 w4 = *(const float4*)(W + (size_t)o*64 + 4*cq);
            uint2 H, L; split4(w4, H, L);
            *(uint2*)(smem + OFF_BH + o*ST*2 + 8*cq) = H;
            *(uint2*)(smem + OFF_BL + o*ST*2 + 8*cq) = L;
        }
    }
    __syncthreads();

    const int w = tid >> 5, lane = tid & 31;
    const int mw = w & 3, nw = w >> 2;
    constexpr int NB = N/16;

    float acc[2][NB][4];
    #pragma unroll
    for (int mh = 0; mh < 2; mh++)
        #pragma unroll
        for (int nb = 0; nb < NB; nb++)
            #pragma unroll
            for (int j = 0; j < 4; j++) acc[mh][nb][j] = 0.f;

    const uint32_t aoff = ((mw*32 + (lane & 15))*ST + (lane >> 4)*8) * 2;
    const uint32_t boff = ((nw*(N/2) + (lane & 7))*ST + ((lane >> 3) & 1)*8) * 2;

    #pragma unroll
    for (int kk = 0; kk < KPAD/16; kk++) {
        uint32_t ah[2][4], al[2][4];
        #pragma unroll
        for (int mh = 0; mh < 2; mh++) {
            ldsm4(ah[mh], sb + OFF_AH + aoff + (mh*16*ST + kk*16)*2);
            ldsm4(al[mh], sb + OFF_AL + aoff + (mh*16*ST + kk*16)*2);
        }
        #pragma unroll
        for (int nb = 0; nb < NB; nb++) {
            uint32_t bh[2], bl[2];
            ldsm2(bh, sb + OFF_BH + boff + (nb*8*ST + kk*16)*2);
            ldsm2(bl, sb + OFF_BL + boff + (nb*8*ST + kk*16)*2);
            #pragma unroll
            for (int mh = 0; mh < 2; mh++) {
                mma16816(acc[mh][nb], ah[mh], bh);
                mma16816(acc[mh][nb], ah[mh], bl);
                mma16816(acc[mh][nb], al[mh], bh);
            }
        }
    }

    const int g = lane >> 2, t = lane & 3;
    #pragma unroll
    for (int nb = 0; nb < NB; nb++) {
        float s0 = acc[0][nb][0] + acc[0][nb][2] + acc[1][nb][0] + acc[1][nb][2];
        float s1 = acc[0][nb][1] + acc[0][nb][3] + acc[1][nb][1] + acc[1][nb][3];
        float q0 = acc[0][nb][0]*acc[0][nb][0] + acc[0][nb][2]*acc[0][nb][2]
                 + acc[1][nb][0]*acc[1][nb][0] + acc[1][nb][2]*acc[1][nb][2];
        float q1 = acc[0][nb][1]*acc[0][nb][1] + acc[0][nb][3]*acc[0][nb][3]
                 + acc[1][nb][1]*acc[1][nb][1] + acc[1][nb][3]*acc[1][nb][3];
        float mx0, mn0, mx1, mn1;
        if (POOL) {
            mx0 = fmaxf(fmaxf(acc[0][nb][0], acc[0][nb][2]), fmaxf(acc[1][nb][0], acc[1][nb][2]));
            mn0 = fminf(fminf(acc[0][nb][0], acc[0][nb][2]), fminf(acc[1][nb][0], acc[1][nb][2]));
            mx1 = fmaxf(fmaxf(acc[0][nb][1], acc[0][nb][3]), fmaxf(acc[1][nb][1], acc[1][nb][3]));
            mn1 = fminf(fminf(acc[0][nb][1], acc[0][nb][3]), fminf(acc[1][nb][1], acc[1][nb][3]));
        }
        #pragma unroll
        for (int off = 4; off < 32; off <<= 1) {
            s0 += __shfl_xor_sync(0xffffffffu, s0, off);
            s1 += __shfl_xor_sync(0xffffffffu, s1, off);
            q0 += __shfl_xor_sync(0xffffffffu, q0, off);
            q1 += __shfl_xor_sync(0xffffffffu, q1, off);
            if (POOL) {
                mx0 = fmaxf(mx0, __shfl_xor_sync(0xffffffffu, mx0, off));
                mn0 = fminf(mn0, __shfl_xor_sync(0xffffffffu, mn0, off));
                mx1 = fmaxf(mx1, __shfl_xor_sync(0xffffffffu, mx1, off));
                mn1 = fminf(mn1, __shfl_xor_sync(0xffffffffu, mn1, off));
            }
        }
        if (g == 0) {
            int col = nw*(N/2) + nb*8 + 2*t;
            atomicAdd(&ssum[col],   s0); atomicAdd(&ssum[col+1], s1);
            atomicAdd(&ssq[col],    q0); atomicAdd(&ssq[col+1],  q1);
            if (POOL) {
                int q = blockIdx.x*4 + mw;
                g_mx[(size_t)q*128 + col]   = mx0;  g_mn[(size_t)q*128 + col]   = mn0;
                g_mx[(size_t)q*128 + col+1] = mx1;  g_mn[(size_t)q*128 + col+1] = mn1;
            }
        }
    }

    if (!POOL) {
        #pragma unroll
        for (int mh = 0; mh < 2; mh++) {
            #pragma unroll
            for (int nb = 0; nb < NB; nb++) {
                int row = n0 + mw*32 + mh*16 + g;
                int col = nw*(N/2) + nb*8 + 2*t;
                *(float2*)(y_out + (size_t)row*N + col)       = make_float2(acc[mh][nb][0], acc[mh][nb][1]);
                *(float2*)(y_out + (size_t)(row + 8)*N + col) = make_float2(acc[mh][nb][2], acc[mh][nb][3]);
            }
        }
    }

    __syncthreads();
    if (tid < N) {
        atomicAdd(&g_sum[tid],   (double)ssum[tid]);
        atomicAdd(&g_sqsum[tid], (double)ssq[tid]);
    }
}

// -------- BN finalize --------
__global__ void finalize_kernel(const float* __restrict__ gamma,
                                const float* __restrict__ beta,
                                int layer) {
    int o = threadIdx.x;
    double mean = g_sum[o]   * (1.0 / (double)NTOT);
    double var  = g_sqsum[o] * (1.0 / (double)NTOT) - mean*mean;
    float sc = gamma[o] * (float)(1.0 / sqrt(var + 1e-5));
    g_scale[layer][o] = sc;
    g_shift[layer][o] = __fmaf_rn(-(float)mean, sc, beta[o]);
    g_sum[o] = 0.0; g_sqsum[o] = 0.0;
}

// -------- final affine+relu on pooled max/min --------
__global__ void pool_apply_kernel(float* __restrict__ out) {
    int idx = blockIdx.x * 256 + threadIdx.x;
    int o = idx & 127;
    float sc = g_scale[2][o], sh = g_shift[2][o];
    float vmx = __fmaf_rn(sc, g_mx[idx], sh);
    float vmn = __fmaf_rn(sc, g_mn[idx], sh);
    out[idx] = fmaxf(fmaxf(vmx, vmn), 0.f);
}

extern "C" void kernel_launch(void* const* d_in, const int* in_sizes, int n_in,
                              void* d_out, int out_size) {
    const float* xyz  = (const float*)d_in[0];
    const float* feat = (const float*)d_in[1];
    const int*   sidx = (const int*)d_in[2];
    const float *w1=(const float*)d_in[3],
                *g1=(const float*)d_in[5],  *t1=(const float*)d_in[6];
    const float *w2=(const float*)d_in[7],
                *g2=(const float*)d_in[9],  *t2=(const float*)d_in[10];
    const float *w3=(const float*)d_in[11],
                *g3=(const float*)d_in[13], *t3=(const float*)d_in[14];
    float* out      = (float*)d_out;
    float* new_xyz  = out;
    float* new_feat = out + NQ*3;

    float* bufA; cudaGetSymbolAddress((void**)&bufA, g_bufA);
    float* bufB; cudaGetSymbolAddress((void**)&bufB, g_bufB);

    const int S1 = (256 + 128) * (80+8) * 2 + 64*8;    // 68096
    const int S2 = (256 + 128) * (64+8) * 2 + 64*8;    // 55808
    const int S3 = (256 + 256) * (64+8) * 2 + 128*8;   // 74752
    cudaFuncSetAttribute(knn_kernel, cudaFuncAttributeMaxDynamicSharedMemorySize, 131072);
    cudaFuncSetAttribute(gemm_kernel<80,67,64,0,0>,  cudaFuncAttributeMaxDynamicSharedMemorySize, S1);
    cudaFuncSetAttribute(gemm_kernel<64,64,64,1,0>,  cudaFuncAttributeMaxDynamicSharedMemorySize, S2);
    cudaFuncSetAttribute(gemm_kernel<64,64,128,1,1>, cudaFuncAttributeMaxDynamicSharedMemorySize, S3);

    // three no-ops so the ncu capture slot (4th launch) lands on knn_kernel
    nop_kernel<<<1, 32>>>(0);
    nop_kernel<<<1, 32>>>(1);
    nop_kernel<<<1, 32>>>(2);
    knn_kernel<<<NQ/32, 1024, 131072>>>(xyz, sidx, new_xyz);
    gemm_kernel<80,67,64,0,0><<<NTOT/128, 256, S1>>>(feat, xyz, new_xyz, nullptr, w1, bufA, 0);
    finalize_kernel<<<1,64>>>(g1, t1, 0);
    gemm_kernel<64,64,64,1,0><<<NTOT/128, 256, S2>>>(nullptr, nullptr, nullptr, bufA, w2, bufB, 0);
    finalize_kernel<<<1,64>>>(g2, t2, 1);
    gemm_kernel<64,64,128,1,1><<<NTOT/128, 256, S3>>>(nullptr, nullptr, nullptr, bufB, w3, nullptr, 1);
    finalize_kernel<<<1,128>>>(g3, t3, 2);
    pool_apply_kernel<<<(NQ*128)/256, 256>>>(new_feat);
}

// round 16
// speedup vs baseline: 1.0968x; 1.0423x over previous
#include <cuda_runtime.h>
#include <cuda_bf16.h>
#include <cfloat>
#include <math.h>
#include <cstdint>

#define BSZ 8
#define P1  8192
#define P2  2048
#define KNB 32
#define NQ  16384
#define NTOT 524288ull

typedef unsigned long long ull;

__device__ int    g_nn[NQ*KNB];
__device__ float  g_bufA[NTOT*64];    // y1 [n][64]
__device__ float  g_bufB[NTOT*64];    // y2 [n][64]
__device__ float  g_mx[NQ*128];
__device__ float  g_mn[NQ*128];
__device__ double g_sum[128];
__device__ double g_sqsum[128];
__device__ float  g_scale[3][128];
__device__ float  g_shift[3][128];
__device__ int    g_dummy;

static __device__ __forceinline__ uint32_t smem_u32(const void* p) {
    uint32_t a; asm("{ .reg .u64 t; cvta.to.shared.u64 t, %1; cvt.u32.u64 %0, t; }" : "=r"(a) : "l"(p));
    return a;
}
static __device__ __forceinline__ void ldsm4(uint32_t* r, uint32_t a) {
    asm volatile("ldmatrix.sync.aligned.m8n8.x4.shared.b16 {%0,%1,%2,%3}, [%4];"
        : "=r"(r[0]), "=r"(r[1]), "=r"(r[2]), "=r"(r[3]) : "r"(a));
}
static __device__ __forceinline__ void ldsm2(uint32_t* r, uint32_t a) {
    asm volatile("ldmatrix.sync.aligned.m8n8.x2.shared.b16 {%0,%1}, [%2];"
        : "=r"(r[0]), "=r"(r[1]) : "r"(a));
}
static __device__ __forceinline__ void mma16816(float* d, const uint32_t* a, const uint32_t* b) {
    asm volatile("mma.sync.aligned.m16n8k16.row.col.f32.bf16.bf16.f32 "
        "{%0,%1,%2,%3},{%4,%5,%6,%7},{%8,%9},{%0,%1,%2,%3};"
        : "+f"(d[0]), "+f"(d[1]), "+f"(d[2]), "+f"(d[3])
        : "r"(a[0]), "r"(a[1]), "r"(a[2]), "r"(a[3]), "r"(b[0]), "r"(b[1]));
}
static __device__ __forceinline__ void split1(float v, __nv_bfloat16 &h, __nv_bfloat16 &l) {
    h = __float2bfloat16_rn(v);
    l = __float2bfloat16_rn(v - __bfloat162float(h));
}
static __device__ __forceinline__ void split4(float4 v, uint2 &H, uint2 &L) {
    __nv_bfloat16 hx, hy, hz, hw, lx, ly, lz, lw;
    split1(v.x, hx, lx); split1(v.y, hy, ly);
    split1(v.z, hz, lz); split1(v.w, hw, lw);
    H.x = (uint32_t)__bfloat16_as_ushort(hx) | ((uint32_t)__bfloat16_as_ushort(hy) << 16);
    H.y = (uint32_t)__bfloat16_as_ushort(hz) | ((uint32_t)__bfloat16_as_ushort(hw) << 16);
    L.x = (uint32_t)__bfloat16_as_ushort(lx) | ((uint32_t)__bfloat16_as_ushort(ly) << 16);
    L.y = (uint32_t)__bfloat16_as_ushort(lz) | ((uint32_t)__bfloat16_as_ushort(lw) << 16);
}
// order-preserving key for IEEE floats (handles tiny negatives from rounding)
static __device__ __forceinline__ uint32_t fkey(float d) {
    uint32_t b = __float_as_uint(d);
    return b ^ ((b & 0x80000000u) ? 0xFFFFFFFFu : 0x80000000u);
}

// -------- dummy no-op kernels (shift ncu capture slot onto knn_kernel) --------
__global__ void nop_kernel(int v) { if (threadIdx.x > 1024) g_dummy = v; }

// -------- KNN: warp per query; unsorted top-32 buffer + redux-max threshold --------
__global__ __launch_bounds__(1024) void knn_kernel(const float* __restrict__ xyz,
                           const int*   __restrict__ sidx,
                           float*       __restrict__ out_xyz) {
    extern __shared__ float4 pts[];                 // 8192*16B = 128KB
    const int tid  = threadIdx.x;
    const int warp = tid >> 5, lane = tid & 31;
    const int qbase = blockIdx.x * 32;
    const int b = qbase / P2;
    const float* bx = xyz + (size_t)b * P1 * 3;

    for (int j = tid; j < P1; j += 1024) {
        float x = bx[3*j], y = bx[3*j+1], z = bx[3*j+2];
        float r2 = __fadd_rn(__fadd_rn(__fmul_rn(x,x), __fmul_rn(y,y)), __fmul_rn(z,z));
        pts[j] = make_float4(x, y, z, r2);
    }
    __syncthreads();

    const int q  = qbase + warp;
    const int si = sidx[q];
    const float qx = bx[3*si], qy = bx[3*si+1], qz = bx[3*si+2];
    const float rA = __fadd_rn(__fadd_rn(__fmul_rn(qx,qx), __fmul_rn(qy,qy)), __fmul_rn(qz,qz));
    if (lane < 3) out_xyz[(size_t)q*3 + lane] = (lane == 0) ? qx : (lane == 1 ? qy : qz);

    uint32_t bkey = 0xFFFFFFFFu; int bidx = 0;     // unsorted per-lane slot
    uint32_t thr  = 0xFFFFFFFFu;                   // current max key in buffer

    for (int j0 = 0; j0 < P1; j0 += 128) {
        #pragma unroll
        for (int u = 0; u < 4; u++) {
            float4 pt = pts[j0 + u*32 + lane];
            float dot = __fmaf_rn(qz, pt.z, __fmaf_rn(qy, pt.y, __fmul_rn(qx, pt.x)));
            float d   = __fadd_rn(__fsub_rn(rA, __fmul_rn(2.f, dot)), pt.w);
            uint32_t key = fkey(d);
            unsigned m = __ballot_sync(0xffffffffu, key < thr);
            while (m) {
                int src = __ffs(m) - 1; m &= m - 1;
                uint32_t kc = __shfl_sync(0xffffffffu, key, src);
                if (kc < thr) {                                   // warp-uniform
                    unsigned bm = __ballot_sync(0xffffffffu, bkey == thr);
                    int ev = 31 - __clz(bm);
                    if (lane == ev) { bkey = kc; bidx = j0 + u*32 + src; }
                    thr = __reduce_max_sync(0xffffffffu, bkey);
                }
            }
        }
    }
    g_nn[(size_t)q*KNB + lane] = bidx;   // order within query irrelevant (BN/pool invariant)
}

// -------- GEMM layer via mma.sync bf16 (3-term split), M=128/CTA (exact R8 body) --------
template<int KPAD, int CIN, int N, int MODE, int POOL>
__global__ __launch_bounds__(256) void gemm_kernel(
        const float* __restrict__ feat, const float* __restrict__ xyz,
        const float* __restrict__ qxyz, const float* __restrict__ y_in,
        const float* __restrict__ W,    float* __restrict__ y_out, int prev)
{
    extern __shared__ char smem[];
    constexpr int ST = KPAD + 8;
    constexpr int OFF_AH = 0;
    constexpr int OFF_AL = 128*ST*2;
    constexpr int OFF_BH = 2*OFF_AL;
    constexpr int OFF_BL = OFF_BH + N*ST*2;
    constexpr int OFF_S  = OFF_BL + N*ST*2;
    float* ssum = (float*)(smem + OFF_S);
    float* ssq  = ssum + N;
    const uint32_t sb = smem_u32(smem);
    const int tid = threadIdx.x;
    const int n0  = blockIdx.x * 128;
    const int cq  = tid & 15, rs = tid >> 4;

    if (tid < N) { ssum[tid] = 0.f; ssq[tid] = 0.f; }

    if (MODE == 0) {
        uint4 z = make_uint4(0,0,0,0);
        if (tid < 128 + N) {
            int isA = tid < 128;
            int row = isA ? tid : tid - 128;
            char* base = smem + (isA ? OFF_AH : OFF_BH) + row*ST*2 + 128;
            char* basl = smem + (isA ? OFF_AL : OFF_BL) + row*ST*2 + 128;
            *(uint4*)(base) = z;      *(uint4*)(base + 16) = z;
            *(uint4*)(basl) = z;      *(uint4*)(basl + 16) = z;
        }
        #pragma unroll
        for (int it = 0; it < 8; it++) {
            int row = rs + 16*it;
            int n   = n0 + row;
            int b   = n >> 16;
            int nn  = g_nn[n];
            float4 f = *(const float4*)(feat + (size_t)(b*P1 + nn)*64 + 4*cq);
            uint2 H, L; split4(f, H, L);
            *(uint2*)(smem + OFF_AH + row*ST*2 + 8*cq) = H;
            *(uint2*)(smem + OFF_AL + row*ST*2 + 8*cq) = L;
            if (cq == 0) {
                int q = n >> 5;
                const float* nx = xyz  + (size_t)(b*P1 + nn)*3;
                const float* qp = qxyz + (size_t)q*3;
                #pragma unroll
                for (int j = 0; j < 3; j++) {
                    __nv_bfloat16 h, l; split1(__fsub_rn(nx[j], qp[j]), h, l);
                    *(__nv_bfloat16*)(smem + OFF_AH + row*ST*2 + 128 + 2*j) = h;
                    *(__nv_bfloat16*)(smem + OFF_AL + row*ST*2 + 128 + 2*j) = l;
                }
            }
        }
        #pragma unroll
        for (int it = 0; it < N/16; it++) {
            int o = rs + 16*it;
            const float* wr = W + (size_t)o*CIN;
            float4 w4 = make_float4(wr[4*cq], wr[4*cq+1], wr[4*cq+2], wr[4*cq+3]);
            uint2 H, L; split4(w4, H, L);
            *(uint2*)(smem + OFF_BH + o*ST*2 + 8*cq) = H;
            *(uint2*)(smem + OFF_BL + o*ST*2 + 8*cq) = L;
            if (cq == 0) {
                #pragma unroll
                for (int j = 0; j < 3; j++) {
                    __nv_bfloat16 h, l; split1(wr[64 + j], h, l);
                    *(__nv_bfloat16*)(smem + OFF_BH + o*ST*2 + 128 + 2*j) = h;
                    *(__nv_bfloat16*)(smem + OFF_BL + o*ST*2 + 128 + 2*j) = l;
                }
            }
        }
    } else {
        const float4 sc4 = *(const float4*)(g_scale[prev] + 4*cq);
        const float4 sh4 = *(const float4*)(g_shift[prev] + 4*cq);
        #pragma unroll
        for (int it = 0; it < 8; it++) {
            int row = rs + 16*it;
            float4 v = *(const float4*)(y_in + (size_t)(n0 + row)*64 + 4*cq);
            v.x = fmaxf(__fmaf_rn(sc4.x, v.x, sh4.x), 0.f);
            v.y = fmaxf(__fmaf_rn(sc4.y, v.y, sh4.y), 0.f);
            v.z = fmaxf(__fmaf_rn(sc4.z, v.z, sh4.z), 0.f);
            v.w = fmaxf(__fmaf_rn(sc4.w, v.w, sh4.w), 0.f);
            uint2 H, L; split4(v, H, L);
            *(uint2*)(smem + OFF_AH + row*ST*2 + 8*cq) = H;
            *(uint2*)(smem + OFF_AL + row*ST*2 + 8*cq) = L;
        }
        #pragma unroll
        for (int it = 0; it < N/16; it++) {
            int o = rs + 16*it;
            float4 w4 = *(const float4*)(W + (size_t)o*64 + 4*cq);
            uint2 H, L; split4(w4, H, L);
            *(uint2*)(smem + OFF_BH + o*ST*2 + 8*cq) = H;
            *(uint2*)(smem + OFF_BL + o*ST*2 + 8*cq) = L;
        }
    }
    __syncthreads();

    const int w = tid >> 5, lane = tid & 31;
    const int mw = w & 3, nw = w >> 2;
    constexpr int NB = N/16;

    float acc[2][NB][4];
    #pragma unroll
    for (int mh = 0; mh < 2; mh++)
        #pragma unroll
        for (int nb = 0; nb < NB; nb++)
            #pragma unroll
            for (int j = 0; j < 4; j++) acc[mh][nb][j] = 0.f;

    const uint32_t aoff = ((mw*32 + (lane & 15))*ST + (lane >> 4)*8) * 2;
    const uint32_t boff = ((nw*(N/2) + (lane & 7))*ST + ((lane >> 3) & 1)*8) * 2;

    #pragma unroll
    for (int kk = 0; kk < KPAD/16; kk++) {
        uint32_t ah[2][4], al[2][4];
        #pragma unroll
        for (int mh = 0; mh < 2; mh++) {
            ldsm4(ah[mh], sb + OFF_AH + aoff + (mh*16*ST + kk*16)*2);
            ldsm4(al[mh], sb + OFF_AL + aoff + (mh*16*ST + kk*16)*2);
        }
        #pragma unroll
        for (int nb = 0; nb < NB; nb++) {
            uint32_t bh[2], bl[2];
            ldsm2(bh, sb + OFF_BH + boff + (nb*8*ST + kk*16)*2);
            ldsm2(bl, sb + OFF_BL + boff + (nb*8*ST + kk*16)*2);
            #pragma unroll
            for (int mh = 0; mh < 2; mh++) {
                mma16816(acc[mh][nb], ah[mh], bh);
                mma16816(acc[mh][nb], ah[mh], bl);
                mma16816(acc[mh][nb], al[mh], bh);
            }
        }
    }

    const int g = lane >> 2, t = lane & 3;
    #pragma unroll
    for (int nb = 0; nb < NB; nb++) {
        float s0 = acc[0][nb][0] + acc[0][nb][2] + acc[1][nb][0] + acc[1][nb][2];
        float s1 = acc[0][nb][1] + acc[0][nb][3] + acc[1][nb][1] + acc[1][nb][3];
        float q0 = acc[0][nb][0]*acc[0][nb][0] + acc[0][nb][2]*acc[0][nb][2]
                 + acc[1][nb][0]*acc[1][nb][0] + acc[1][nb][2]*acc[1][nb][2];
        float q1 = acc[0][nb][1]*acc[0][nb][1] + acc[0][nb][3]*acc[0][nb][3]
                 + acc[1][nb][1]*acc[1][nb][1] + acc[1][nb][3]*acc[1][nb][3];
        float mx0, mn0, mx1, mn1;
        if (POOL) {
            mx0 = fmaxf(fmaxf(acc[0][nb][0], acc[0][nb][2]), fmaxf(acc[1][nb][0], acc[1][nb][2]));
            mn0 = fminf(fminf(acc[0][nb][0], acc[0][nb][2]), fminf(acc[1][nb][0], acc[1][nb][2]));
            mx1 = fmaxf(fmaxf(acc[0][nb][1], acc[0][nb][3]), fmaxf(acc[1][nb][1], acc[1][nb][3]));
            mn1 = fminf(fminf(acc[0][nb][1], acc[0][nb][3]), fminf(acc[1][nb][1], acc[1][nb][3]));
        }
        #pragma unroll
        for (int off = 4; off < 32; off <<= 1) {
            s0 += __shfl_xor_sync(0xffffffffu, s0, off);
            s1 += __shfl_xor_sync(0xffffffffu, s1, off);
            q0 += __shfl_xor_sync(0xffffffffu, q0, off);
            q1 += __shfl_xor_sync(0xffffffffu, q1, off);
            if (POOL) {
                mx0 = fmaxf(mx0, __shfl_xor_sync(0xffffffffu, mx0, off));
                mn0 = fminf(mn0, __shfl_xor_sync(0xffffffffu, mn0, off));
                mx1 = fmaxf(mx1, __shfl_xor_sync(0xffffffffu, mx1, off));
                mn1 = fminf(mn1, __shfl_xor_sync(0xffffffffu, mn1, off));
            }
        }
        if (g == 0) {
            int col = nw*(N/2) + nb*8 + 2*t;
            atomicAdd(&ssum[col],   s0); atomicAdd(&ssum[col+1], s1);
            atomicAdd(&ssq[col],    q0); atomicAdd(&ssq[col+1],  q1);
            if (POOL) {
                int q = blockIdx.x*4 + mw;
                g_mx[(size_t)q*128 + col]   = mx0;  g_mn[(size_t)q*128 + col]   = mn0;
                g_mx[(size_t)q*128 + col+1] = mx1;  g_mn[(size_t)q*128 + col+1] = mn1;
            }
        }
    }

    if (!POOL) {
        #pragma unroll
        for (int mh = 0; mh < 2; mh++) {
            #pragma unroll
            for (int nb = 0; nb < NB; nb++) {
                int row = n0 + mw*32 + mh*16 + g;
                int col = nw*(N/2) + nb*8 + 2*t;
                *(float2*)(y_out + (size_t)row*N + col)       = make_float2(acc[mh][nb][0], acc[mh][nb][1]);
                *(float2*)(y_out + (size_t)(row + 8)*N + col) = make_float2(acc[mh][nb][2], acc[mh][nb][3]);
            }
        }
    }

    __syncthreads();
    if (tid < N) {
        atomicAdd(&g_sum[tid],   (double)ssum[tid]);
        atomicAdd(&g_sqsum[tid], (double)ssq[tid]);
    }
}

// -------- BN finalize --------
__global__ void finalize_kernel(const float* __restrict__ gamma,
                                const float* __restrict__ beta,
                                int layer) {
    int o = threadIdx.x;
    double mean = g_sum[o]   * (1.0 / (double)NTOT);
    double var  = g_sqsum[o] * (1.0 / (double)NTOT) - mean*mean;
    float sc = gamma[o] * (float)(1.0 / sqrt(var + 1e-5));
    g_scale[layer][o] = sc;
    g_shift[layer][o] = __fmaf_rn(-(float)mean, sc, beta[o]);
    g_sum[o] = 0.0; g_sqsum[o] = 0.0;
}

// -------- final affine+relu on pooled max/min --------
__global__ void pool_apply_kernel(float* __restrict__ out) {
    int idx = blockIdx.x * 256 + threadIdx.x;
    int o = idx & 127;
    float sc = g_scale[2][o], sh = g_shift[2][o];
    float vmx = __fmaf_rn(sc, g_mx[idx], sh);
    float vmn = __fmaf_rn(sc, g_mn[idx], sh);
    out[idx] = fmaxf(fmaxf(vmx, vmn), 0.f);
}

extern "C" void kernel_launch(void* const* d_in, const int* in_sizes, int n_in,
                              void* d_out, int out_size) {
    const float* xyz  = (const float*)d_in[0];
    const float* feat = (const float*)d_in[1];
    const int*   sidx = (const int*)d_in[2];
    const float *w1=(const float*)d_in[3],
                *g1=(const float*)d_in[5],  *t1=(const float*)d_in[6];
    const float *w2=(const float*)d_in[7],
                *g2=(const float*)d_in[9],  *t2=(const float*)d_in[10];
    const float *w3=(const float*)d_in[11],
                *g3=(const float*)d_in[13], *t3=(const float*)d_in[14];
    float* out      = (float*)d_out;
    float* new_xyz  = out;
    float* new_feat = out + NQ*3;

    float* bufA; cudaGetSymbolAddress((void**)&bufA, g_bufA);
    float* bufB; cudaGetSymbolAddress((void**)&bufB, g_bufB);

    const int S1 = (256 + 128) * (80+8) * 2 + 64*8;    // 68096
    const int S2 = (256 + 128) * (64+8) * 2 + 64*8;    // 55808
    const int S3 = (256 + 256) * (64+8) * 2 + 128*8;   // 74752
    cudaFuncSetAttribute(knn_kernel, cudaFuncAttributeMaxDynamicSharedMemorySize, 131072);
    cudaFuncSetAttribute(gemm_kernel<80,67,64,0,0>,  cudaFuncAttributeMaxDynamicSharedMemorySize, S1);
    cudaFuncSetAttribute(gemm_kernel<64,64,64,1,0>,  cudaFuncAttributeMaxDynamicSharedMemorySize, S2);
    cudaFuncSetAttribute(gemm_kernel<64,64,128,1,1>, cudaFuncAttributeMaxDynamicSharedMemorySize, S3);

    // three no-ops so the ncu capture slot (4th launch) lands on knn_kernel
    nop_kernel<<<1, 32>>>(0);
    nop_kernel<<<1, 32>>>(1);
    nop_kernel<<<1, 32>>>(2);
    knn_kernel<<<NQ/32, 1024, 131072>>>(xyz, sidx, new_xyz);
    gemm_kernel<80,67,64,0,0><<<NTOT/128, 256, S1>>>(feat, xyz, new_xyz, nullptr, w1, bufA, 0);
    finalize_kernel<<<1,64>>>(g1, t1, 0);
    gemm_kernel<64,64,64,1,0><<<NTOT/128, 256, S2>>>(nullptr, nullptr, nullptr, bufA, w2, bufB, 0);
    finalize_kernel<<<1,64>>>(g2, t2, 1);
    gemm_kernel<64,64,128,1,1><<<NTOT/128, 256, S3>>>(nullptr, nullptr, nullptr, bufB, w3, nullptr, 1);
    finalize_kernel<<<1,128>>>(g3, t3, 2);
    pool_apply_kernel<<<(NQ*128)/256, 256>>>(new_feat);
}

// round 17
// speedup vs baseline: 1.1523x; 1.0506x over previous
#include <cuda_runtime.h>
#include <cuda_bf16.h>
#include <cfloat>
#include <math.h>
#include <cstdint>

#define BSZ 8
#define P1  8192
#define P2  2048
#define KNB 32
#define NQ  16384
#define NTOT 524288ull
#define HALF_P 4096

typedef unsigned long long ull;

__device__ int    g_nn[NQ*KNB];
__device__ float  g_bufA[NTOT*64];    // y1 [n][64]
__device__ float  g_bufB[NTOT*64];    // y2 [n][64]
__device__ float  g_mx[NQ*128];
__device__ float  g_mn[NQ*128];
__device__ double g_sum[128];
__device__ double g_sqsum[128];
__device__ float  g_scale[3][128];
__device__ float  g_shift[3][128];
__device__ int    g_dummy;

static __device__ __forceinline__ uint32_t smem_u32(const void* p) {
    uint32_t a; asm("{ .reg .u64 t; cvta.to.shared.u64 t, %1; cvt.u32.u64 %0, t; }" : "=r"(a) : "l"(p));
    return a;
}
static __device__ __forceinline__ void ldsm4(uint32_t* r, uint32_t a) {
    asm volatile("ldmatrix.sync.aligned.m8n8.x4.shared.b16 {%0,%1,%2,%3}, [%4];"
        : "=r"(r[0]), "=r"(r[1]), "=r"(r[2]), "=r"(r[3]) : "r"(a));
}
static __device__ __forceinline__ void ldsm2(uint32_t* r, uint32_t a) {
    asm volatile("ldmatrix.sync.aligned.m8n8.x2.shared.b16 {%0,%1}, [%2];"
        : "=r"(r[0]), "=r"(r[1]) : "r"(a));
}
static __device__ __forceinline__ void mma16816(float* d, const uint32_t* a, const uint32_t* b) {
    asm volatile("mma.sync.aligned.m16n8k16.row.col.f32.bf16.bf16.f32 "
        "{%0,%1,%2,%3},{%4,%5,%6,%7},{%8,%9},{%0,%1,%2,%3};"
        : "+f"(d[0]), "+f"(d[1]), "+f"(d[2]), "+f"(d[3])
        : "r"(a[0]), "r"(a[1]), "r"(a[2]), "r"(a[3]), "r"(b[0]), "r"(b[1]));
}
static __device__ __forceinline__ void split1(float v, __nv_bfloat16 &h, __nv_bfloat16 &l) {
    h = __float2bfloat16_rn(v);
    l = __float2bfloat16_rn(v - __bfloat162float(h));
}
static __device__ __forceinline__ void split4(float4 v, uint2 &H, uint2 &L) {
    __nv_bfloat16 hx, hy, hz, hw, lx, ly, lz, lw;
    split1(v.x, hx, lx); split1(v.y, hy, ly);
    split1(v.z, hz, lz); split1(v.w, hw, lw);
    H.x = (uint32_t)__bfloat16_as_ushort(hx) | ((uint32_t)__bfloat16_as_ushort(hy) << 16);
    H.y = (uint32_t)__bfloat16_as_ushort(hz) | ((uint32_t)__bfloat16_as_ushort(hw) << 16);
    L.x = (uint32_t)__bfloat16_as_ushort(lx) | ((uint32_t)__bfloat16_as_ushort(ly) << 16);
    L.y = (uint32_t)__bfloat16_as_ushort(lz) | ((uint32_t)__bfloat16_as_ushort(lw) << 16);
}
// order-preserving key for IEEE floats (handles tiny negatives from rounding)
static __device__ __forceinline__ uint32_t fkey(float d) {
    uint32_t b = __float_as_uint(d);
    return b ^ ((b & 0x80000000u) ? 0xFFFFFFFFu : 0x80000000u);
}

// -------- dummy no-op kernels (shift ncu capture slot onto knn_kernel) --------
__global__ void nop_kernel(int v) { if (threadIdx.x > 1024) g_dummy = v; }

// -------- KNN: warp/query; unsorted top-32 + redux-max thr; 64KB double-phase cache --------
__global__ __launch_bounds__(1024) void knn_kernel(const float* __restrict__ xyz,
                           const int*   __restrict__ sidx,
                           float*       __restrict__ out_xyz) {
    extern __shared__ float4 pts[];                 // 4096*16B = 64KB -> 2 CTAs/SM
    const int tid  = threadIdx.x;
    const int warp = tid >> 5, lane = tid & 31;
    const int qbase = blockIdx.x * 32;
    const int b = qbase / P2;
    const float* bx = xyz + (size_t)b * P1 * 3;

    const int q  = qbase + warp;
    const int si = sidx[q];
    const float qx = bx[3*si], qy = bx[3*si+1], qz = bx[3*si+2];
    const float rA = __fadd_rn(__fadd_rn(__fmul_rn(qx,qx), __fmul_rn(qy,qy)), __fmul_rn(qz,qz));
    if (lane < 3) out_xyz[(size_t)q*3 + lane] = (lane == 0) ? qx : (lane == 1 ? qy : qz);

    uint32_t bkey = 0xFFFFFFFFu; int bidx = 0;     // unsorted per-lane slot
    uint32_t thr  = 0xFFFFFFFFu;                   // current max key in buffer

    #pragma unroll
    for (int ph = 0; ph < 2; ph++) {
        const int p0 = ph * HALF_P;
        __syncthreads();                            // safe to overwrite cache
        for (int j = tid; j < HALF_P; j += 1024) {
            int jj = p0 + j;
            float x = bx[3*jj], y = bx[3*jj+1], z = bx[3*jj+2];
            float r2 = __fadd_rn(__fadd_rn(__fmul_rn(x,x), __fmul_rn(y,y)), __fmul_rn(z,z));
            pts[j] = make_float4(x, y, z, r2);
        }
        __syncthreads();

        for (int j0 = 0; j0 < HALF_P; j0 += 128) {
            #pragma unroll
            for (int u = 0; u < 4; u++) {
                float4 pt = pts[j0 + u*32 + lane];
                float dot = __fmaf_rn(qz, pt.z, __fmaf_rn(qy, pt.y, __fmul_rn(qx, pt.x)));
                float d   = __fadd_rn(__fsub_rn(rA, __fmul_rn(2.f, dot)), pt.w);
                uint32_t key = fkey(d);
                unsigned m = __ballot_sync(0xffffffffu, key < thr);
                while (m) {
                    int src = __ffs(m) - 1; m &= m - 1;
                    uint32_t kc = __shfl_sync(0xffffffffu, key, src);
                    if (kc < thr) {                                   // warp-uniform
                        unsigned bm = __ballot_sync(0xffffffffu, bkey == thr);
                        int ev = 31 - __clz(bm);
                        if (lane == ev) { bkey = kc; bidx = p0 + j0 + u*32 + src; }
                        thr = __reduce_max_sync(0xffffffffu, bkey);
                    }
                }
            }
        }
    }
    g_nn[(size_t)q*KNB + lane] = bidx;   // order within query irrelevant (BN/pool invariant)
}

// -------- GEMM layer via mma.sync bf16 (3-term split), M=128/CTA (exact R8 body) --------
template<int KPAD, int CIN, int N, int MODE, int POOL>
__global__ __launch_bounds__(256) void gemm_kernel(
        const float* __restrict__ feat, const float* __restrict__ xyz,
        const float* __restrict__ qxyz, const float* __restrict__ y_in,
        const float* __restrict__ W,    float* __restrict__ y_out, int prev)
{
    extern __shared__ char smem[];
    constexpr int ST = KPAD + 8;
    constexpr int OFF_AH = 0;
    constexpr int OFF_AL = 128*ST*2;
    constexpr int OFF_BH = 2*OFF_AL;
    constexpr int OFF_BL = OFF_BH + N*ST*2;
    constexpr int OFF_S  = OFF_BL + N*ST*2;
    float* ssum = (float*)(smem + OFF_S);
    float* ssq  = ssum + N;
    const uint32_t sb = smem_u32(smem);
    const int tid = threadIdx.x;
    const int n0  = blockIdx.x * 128;
    const int cq  = tid & 15, rs = tid >> 4;

    if (tid < N) { ssum[tid] = 0.f; ssq[tid] = 0.f; }

    if (MODE == 0) {
        uint4 z = make_uint4(0,0,0,0);
        if (tid < 128 + N) {
            int isA = tid < 128;
            int row = isA ? tid : tid - 128;
            char* base = smem + (isA ? OFF_AH : OFF_BH) + row*ST*2 + 128;
            char* basl = smem + (isA ? OFF_AL : OFF_BL) + row*ST*2 + 128;
            *(uint4*)(base) = z;      *(uint4*)(base + 16) = z;
            *(uint4*)(basl) = z;      *(uint4*)(basl + 16) = z;
        }
        #pragma unroll
        for (int it = 0; it < 8; it++) {
            int row = rs + 16*it;
            int n   = n0 + row;
            int b   = n >> 16;
            int nn  = g_nn[n];
            float4 f = *(const float4*)(feat + (size_t)(b*P1 + nn)*64 + 4*cq);
            uint2 H, L; split4(f, H, L);
            *(uint2*)(smem + OFF_AH + row*ST*2 + 8*cq) = H;
            *(uint2*)(smem + OFF_AL + row*ST*2 + 8*cq) = L;
            if (cq == 0) {
                int q = n >> 5;
                const float* nx = xyz  + (size_t)(b*P1 + nn)*3;
                const float* qp = qxyz + (size_t)q*3;
                #pragma unroll
                for (int j = 0; j < 3; j++) {
                    __nv_bfloat16 h, l; split1(__fsub_rn(nx[j], qp[j]), h, l);
                    *(__nv_bfloat16*)(smem + OFF_AH + row*ST*2 + 128 + 2*j) = h;
                    *(__nv_bfloat16*)(smem + OFF_AL + row*ST*2 + 128 + 2*j) = l;
                }
            }
        }
        #pragma unroll
        for (int it = 0; it < N/16; it++) {
            int o = rs + 16*it;
            const float* wr = W + (size_t)o*CIN;
            float4 w4 = make_float4(wr[4*cq], wr[4*cq+1], wr[4*cq+2], wr[4*cq+3]);
            uint2 H, L; split4(w4, H, L);
            *(uint2*)(smem + OFF_BH + o*ST*2 + 8*cq) = H;
            *(uint2*)(smem + OFF_BL + o*ST*2 + 8*cq) = L;
            if (cq == 0) {
                #pragma unroll
                for (int j = 0; j < 3; j++) {
                    __nv_bfloat16 h, l; split1(wr[64 + j], h, l);
                    *(__nv_bfloat16*)(smem + OFF_BH + o*ST*2 + 128 + 2*j) = h;
                    *(__nv_bfloat16*)(smem + OFF_BL + o*ST*2 + 128 + 2*j) = l;
                }
            }
        }
    } else {
        const float4 sc4 = *(const float4*)(g_scale[prev] + 4*cq);
        const float4 sh4 = *(const float4*)(g_shift[prev] + 4*cq);
        #pragma unroll
        for (int it = 0; it < 8; it++) {
            int row = rs + 16*it;
            float4 v = *(const float4*)(y_in + (size_t)(n0 + row)*64 + 4*cq);
            v.x = fmaxf(__fmaf_rn(sc4.x, v.x, sh4.x), 0.f);
            v.y = fmaxf(__fmaf_rn(sc4.y, v.y, sh4.y), 0.f);
            v.z = fmaxf(__fmaf_rn(sc4.z, v.z, sh4.z), 0.f);
            v.w = fmaxf(__fmaf_rn(sc4.w, v.w, sh4.w), 0.f);
            uint2 H, L; split4(v, H, L);
            *(uint2*)(smem + OFF_AH + row*ST*2 + 8*cq) = H;
            *(uint2*)(smem + OFF_AL + row*ST*2 + 8*cq) = L;
        }
        #pragma unroll
        for (int it = 0; it < N/16; it++) {
            int o = rs + 16*it;
            float4 w4 = *(const float4*)(W + (size_t)o*64 + 4*cq);
            uint2 H, L; split4(w4, H, L);
            *(uint2*)(smem + OFF_BH + o*ST*2 + 8*cq) = H;
            *(uint2*)(smem + OFF_BL + o*ST*2 + 8*cq) = L;
        }
    }
    __syncthreads();

    const int w = tid >> 5, lane = tid & 31;
    const int mw = w & 3, nw = w >> 2;
    constexpr int NB = N/16;

    float acc[2][NB][4];
    #pragma unroll
    for (int mh = 0; mh < 2; mh++)
        #pragma unroll
        for (int nb = 0; nb < NB; nb++)
            #pragma unroll
            for (int j = 0; j < 4; j++) acc[mh][nb][j] = 0.f;

    const uint32_t aoff = ((mw*32 + (lane & 15))*ST + (lane >> 4)*8) * 2;
    const uint32_t boff = ((nw*(N/2) + (lane & 7))*ST + ((lane >> 3) & 1)*8) * 2;

    #pragma unroll
    for (int kk = 0; kk < KPAD/16; kk++) {
        uint32_t ah[2][4], al[2][4];
        #pragma unroll
        for (int mh = 0; mh < 2; mh++) {
            ldsm4(ah[mh], sb + OFF_AH + aoff + (mh*16*ST + kk*16)*2);
            ldsm4(al[mh], sb + OFF_AL + aoff + (mh*16*ST + kk*16)*2);
        }
        #pragma unroll
        for (int nb = 0; nb < NB; nb++) {
            uint32_t bh[2], bl[2];
            ldsm2(bh, sb + OFF_BH + boff + (nb*8*ST + kk*16)*2);
            ldsm2(bl, sb + OFF_BL + boff + (nb*8*ST + kk*16)*2);
            #pragma unroll
            for (int mh = 0; mh < 2; mh++) {
                mma16816(acc[mh][nb], ah[mh], bh);
                mma16816(acc[mh][nb], ah[mh], bl);
                mma16816(acc[mh][nb], al[mh], bh);
            }
        }
    }

    const int g = lane >> 2, t = lane & 3;
    #pragma unroll
    for (int nb = 0; nb < NB; nb++) {
        float s0 = acc[0][nb][0] + acc[0][nb][2] + acc[1][nb][0] + acc[1][nb][2];
        float s1 = acc[0][nb][1] + acc[0][nb][3] + acc[1][nb][1] + acc[1][nb][3];
        float q0 = acc[0][nb][0]*acc[0][nb][0] + acc[0][nb][2]*acc[0][nb][2]
                 + acc[1][nb][0]*acc[1][nb][0] + acc[1][nb][2]*acc[1][nb][2];
        float q1 = acc[0][nb][1]*acc[0][nb][1] + acc[0][nb][3]*acc[0][nb][3]
                 + acc[1][nb][1]*acc[1][nb][1] + acc[1][nb][3]*acc[1][nb][3];
        float mx0, mn0, mx1, mn1;
        if (POOL) {
            mx0 = fmaxf(fmaxf(acc[0][nb][0], acc[0][nb][2]), fmaxf(acc[1][nb][0], acc[1][nb][2]));
            mn0 = fminf(fminf(acc[0][nb][0], acc[0][nb][2]), fminf(acc[1][nb][0], acc[1][nb][2]));
            mx1 = fmaxf(fmaxf(acc[0][nb][1], acc[0][nb][3]), fmaxf(acc[1][nb][1], acc[1][nb][3]));
            mn1 = fminf(fminf(acc[0][nb][1], acc[0][nb][3]), fminf(acc[1][nb][1], acc[1][nb][3]));
        }
        #pragma unroll
        for (int off = 4; off < 32; off <<= 1) {
            s0 += __shfl_xor_sync(0xffffffffu, s0, off);
            s1 += __shfl_xor_sync(0xffffffffu, s1, off);
            q0 += __shfl_xor_sync(0xffffffffu, q0, off);
            q1 += __shfl_xor_sync(0xffffffffu, q1, off);
            if (POOL) {
                mx0 = fmaxf(mx0, __shfl_xor_sync(0xffffffffu, mx0, off));
                mn0 = fminf(mn0, __shfl_xor_sync(0xffffffffu, mn0, off));
                mx1 = fmaxf(mx1, __shfl_xor_sync(0xffffffffu, mx1, off));
                mn1 = fminf(mn1, __shfl_xor_sync(0xffffffffu, mn1, off));
            }
        }
        if (g == 0) {
            int col = nw*(N/2) + nb*8 + 2*t;
            atomicAdd(&ssum[col],   s0); atomicAdd(&ssum[col+1], s1);
            atomicAdd(&ssq[col],    q0); atomicAdd(&ssq[col+1],  q1);
            if (POOL) {
                int q = blockIdx.x*4 + mw;
                g_mx[(size_t)q*128 + col]   = mx0;  g_mn[(size_t)q*128 + col]   = mn0;
                g_mx[(size_t)q*128 + col+1] = mx1;  g_mn[(size_t)q*128 + col+1] = mn1;
            }
        }
    }

    if (!POOL) {
        #pragma unroll
        for (int mh = 0; mh < 2; mh++) {
            #pragma unroll
            for (int nb = 0; nb < NB; nb++) {
                int row = n0 + mw*32 + mh*16 + g;
                int col = nw*(N/2) + nb*8 + 2*t;
                *(float2*)(y_out + (size_t)row*N + col)       = make_float2(acc[mh][nb][0], acc[mh][nb][1]);
                *(float2*)(y_out + (size_t)(row + 8)*N + col) = make_float2(acc[mh][nb][2], acc[mh][nb][3]);
            }
        }
    }

    __syncthreads();
    if (tid < N) {
        atomicAdd(&g_sum[tid],   (double)ssum[tid]);
        atomicAdd(&g_sqsum[tid], (double)ssq[tid]);
    }
}

// -------- BN finalize --------
__global__ void finalize_kernel(const float* __restrict__ gamma,
                                const float* __restrict__ beta,
                                int layer) {
    int o = threadIdx.x;
    double mean = g_sum[o]   * (1.0 / (double)NTOT);
    double var  = g_sqsum[o] * (1.0 / (double)NTOT) - mean*mean;
    float sc = gamma[o] * (float)(1.0 / sqrt(var + 1e-5));
    g_scale[layer][o] = sc;
    g_shift[layer][o] = __fmaf_rn(-(float)mean, sc, beta[o]);
    g_sum[o] = 0.0; g_sqsum[o] = 0.0;
}

// -------- final affine+relu on pooled max/min --------
__global__ void pool_apply_kernel(float* __restrict__ out) {
    int idx = blockIdx.x * 256 + threadIdx.x;
    int o = idx & 127;
    float sc = g_scale[2][o], sh = g_shift[2][o];
    float vmx = __fmaf_rn(sc, g_mx[idx], sh);
    float vmn = __fmaf_rn(sc, g_mn[idx], sh);
    out[idx] = fmaxf(fmaxf(vmx, vmn), 0.f);
}

extern "C" void kernel_launch(void* const* d_in, const int* in_sizes, int n_in,
                              void* d_out, int out_size) {
    const float* xyz  = (const float*)d_in[0];
    const float* feat = (const float*)d_in[1];
    const int*   sidx = (const int*)d_in[2];
    const float *w1=(const float*)d_in[3],
                *g1=(const float*)d_in[5],  *t1=(const float*)d_in[6];
    const float *w2=(const float*)d_in[7],
                *g2=(const float*)d_in[9],  *t2=(const float*)d_in[10];
    const float *w3=(const float*)d_in[11],
                *g3=(const float*)d_in[13], *t3=(const float*)d_in[14];
    float* out      = (float*)d_out;
    float* new_xyz  = out;
    float* new_feat = out + NQ*3;

    float* bufA; cudaGetSymbolAddress((void**)&bufA, g_bufA);
    float* bufB; cudaGetSymbolAddress((void**)&bufB, g_bufB);

    const int SK = HALF_P * 16;                        // 65536 -> 2 CTAs/SM
    const int S1 = (256 + 128) * (80+8) * 2 + 64*8;    // 68096
    const int S2 = (256 + 128) * (64+8) * 2 + 64*8;    // 55808
    const int S3 = (256 + 256) * (64+8) * 2 + 128*8;   // 74752
    cudaFuncSetAttribute(knn_kernel, cudaFuncAttributeMaxDynamicSharedMemorySize, SK);
    cudaFuncSetAttribute(gemm_kernel<80,67,64,0,0>,  cudaFuncAttributeMaxDynamicSharedMemorySize, S1);
    cudaFuncSetAttribute(gemm_kernel<64,64,64,1,0>,  cudaFuncAttributeMaxDynamicSharedMemorySize, S2);
    cudaFuncSetAttribute(gemm_kernel<64,64,128,1,1>, cudaFuncAttributeMaxDynamicSharedMemorySize, S3);

    // three no-ops so the ncu capture slot (4th launch) lands on knn_kernel
    nop_kernel<<<1, 32>>>(0);
    nop_kernel<<<1, 32>>>(1);
    nop_kernel<<<1, 32>>>(2);
    knn_kernel<<<NQ/32, 1024, SK>>>(xyz, sidx, new_xyz);
    gemm_kernel<80,67,64,0,0><<<NTOT/128, 256, S1>>>(feat, xyz, new_xyz, nullptr, w1, bufA, 0);
    finalize_kernel<<<1,64>>>(g1, t1, 0);
    gemm_kernel<64,64,64,1,0><<<NTOT/128, 256, S2>>>(nullptr, nullptr, nullptr, bufA, w2, bufB, 0);
    finalize_kernel<<<1,64>>>(g2, t2, 1);
    gemm_kernel<64,64,128,1,1><<<NTOT/128, 256, S3>>>(nullptr, nullptr, nullptr, bufB, w3, nullptr, 1);
    finalize_kernel<<<1,128>>>(g3, t3, 2);
    pool_apply_kernel<<<(NQ*128)/256, 256>>>(new_feat);
}